// round 1
// baseline (speedup 1.0000x reference)
#include <cuda_runtime.h>
#include <math.h>

// Problem dims (fixed by dataset)
#define N_NODES 50000
#define N_EDGES 500000
#define C_IN    256
#define H       128
#define H2      256
#define NLAYERS 4
#define NGRAPH  64
#define KCLIN   8
#define NCLS    2
#define EPS_MSG 1e-7f
#define EPS_BN  1e-5f

// Scratch (device globals; no allocation allowed)
__device__ float g_xs [N_NODES * H];
__device__ float g_xd [N_NODES * H];
__device__ float g_h  [N_NODES * H];
__device__ float g_num[N_NODES * H];
__device__ float g_den[N_NODES * H];
__device__ float g_out[N_NODES * H];
__device__ float g_mid[N_NODES * H2];
__device__ float g_pool[NGRAPH * H];
__device__ float g_cnt [NGRAPH];

// ---------------------------------------------------------------------------
// Zero the accumulators (num/den for layer 0; pool/cnt for the epilogue).
// agg_kernel re-zeros num/den for subsequent layers.
// ---------------------------------------------------------------------------
__global__ void zero_kernel() {
    int i = blockIdx.x * blockDim.x + threadIdx.x;
    int stride = gridDim.x * blockDim.x;
    const int n4 = N_NODES * H / 4;
    float4 z = make_float4(0.f, 0.f, 0.f, 0.f);
    for (int k = i; k < n4; k += stride) {
        reinterpret_cast<float4*>(g_num)[k] = z;
        reinterpret_cast<float4*>(g_den)[k] = z;
    }
    for (int k = i; k < NGRAPH * H; k += stride) g_pool[k] = 0.f;
    if (i < NGRAPH) g_cnt[i] = 0.f;
}

// ---------------------------------------------------------------------------
// Edge pass: one warp per edge. Softmax aggregation WITHOUT the max-shift:
//   exp(z - zmax) cancels between numerator and denominator; z is small here
//   (msg = relu(..)+eps, t ~ 0.1) so exp(z) cannot overflow.
// Accumulate denom += exp(z), num += msg*exp(z) with coalesced atomics.
// ---------------------------------------------------------------------------
__global__ void edge_kernel(const int* __restrict__ src,
                            const int* __restrict__ dst,
                            const float* __restrict__ eattr,
                            const float* __restrict__ xs,
                            const float* __restrict__ ew,
                            const float* __restrict__ eb,
                            const float* __restrict__ tptr, int l)
{
    int lane = threadIdx.x & 31;
    int warp = (blockIdx.x * blockDim.x + threadIdx.x) >> 5;
    int nw   = (gridDim.x * blockDim.x) >> 5;
    int c0   = lane * 4;

    float4 w4 = *reinterpret_cast<const float4*>(ew + c0);
    float4 b4 = *reinterpret_cast<const float4*>(eb + c0);
    float  tv = tptr[l];

    for (int e = warp; e < N_EDGES; e += nw) {
        int   s  = src[e];
        int   d  = dst[e];
        float al = eattr[e];
        float4 x4 = *reinterpret_cast<const float4*>(xs + (long)s * H + c0);

        float m0 = fmaxf(fmaf(al, w4.x, b4.x) + x4.x, 0.f) + EPS_MSG;
        float m1 = fmaxf(fmaf(al, w4.y, b4.y) + x4.y, 0.f) + EPS_MSG;
        float m2 = fmaxf(fmaf(al, w4.z, b4.z) + x4.z, 0.f) + EPS_MSG;
        float m3 = fmaxf(fmaf(al, w4.w, b4.w) + x4.w, 0.f) + EPS_MSG;

        float e0 = expf(m0 * tv);
        float e1 = expf(m1 * tv);
        float e2 = expf(m2 * tv);
        float e3 = expf(m3 * tv);

        float* dp = g_den + (long)d * H + c0;
        atomicAdd(dp + 0, e0);
        atomicAdd(dp + 1, e1);
        atomicAdd(dp + 2, e2);
        atomicAdd(dp + 3, e3);
        float* np = g_num + (long)d * H + c0;
        atomicAdd(np + 0, m0 * e0);
        atomicAdd(np + 1, m1 * e1);
        atomicAdd(np + 2, m2 * e2);
        atomicAdd(np + 3, m3 * e3);
    }
}

// ---------------------------------------------------------------------------
// agg: out = num / max(den, 1e-16) + xd ; and re-zero num/den for next layer.
// ---------------------------------------------------------------------------
__global__ void agg_kernel(const float* __restrict__ xd)
{
    int i = blockIdx.x * blockDim.x + threadIdx.x;
    int stride = gridDim.x * blockDim.x;
    const int n4 = N_NODES * H / 4;
    float4 z = make_float4(0.f, 0.f, 0.f, 0.f);
    for (int k = i; k < n4; k += stride) {
        float4 nm = reinterpret_cast<float4*>(g_num)[k];
        float4 dn = reinterpret_cast<float4*>(g_den)[k];
        float4 xv = reinterpret_cast<const float4*>(xd)[k];
        float4 o;
        o.x = nm.x / fmaxf(dn.x, 1e-16f) + xv.x;
        o.y = nm.y / fmaxf(dn.y, 1e-16f) + xv.y;
        o.z = nm.z / fmaxf(dn.z, 1e-16f) + xv.z;
        o.w = nm.w / fmaxf(dn.w, 1e-16f) + xv.w;
        reinterpret_cast<float4*>(g_out)[k] = o;
        reinterpret_cast<float4*>(g_num)[k] = z;
        reinterpret_cast<float4*>(g_den)[k] = z;
    }
}

// ---------------------------------------------------------------------------
// r = relu(batchnorm(h)) elementwise (pre-norm for layers 1..L-1)
// ---------------------------------------------------------------------------
__global__ void relubn_kernel(const float* __restrict__ h,
                              const float* __restrict__ gg,
                              const float* __restrict__ gb,
                              const float* __restrict__ gm,
                              const float* __restrict__ gv,
                              float* __restrict__ r)
{
    int i = blockIdx.x * blockDim.x + threadIdx.x;
    int stride = gridDim.x * blockDim.x;
    const int n4 = N_NODES * H / 4;
    for (int k = i; k < n4; k += stride) {
        int c0 = (k * 4) & (H - 1);
        float4 hv = reinterpret_cast<const float4*>(h)[k];
        float4 g4 = *reinterpret_cast<const float4*>(gg + c0);
        float4 b4 = *reinterpret_cast<const float4*>(gb + c0);
        float4 m4 = *reinterpret_cast<const float4*>(gm + c0);
        float4 v4 = *reinterpret_cast<const float4*>(gv + c0);
        float4 o;
        o.x = fmaxf((hv.x - m4.x) * (g4.x * rsqrtf(v4.x + EPS_BN)) + b4.x, 0.f);
        o.y = fmaxf((hv.y - m4.y) * (g4.y * rsqrtf(v4.y + EPS_BN)) + b4.y, 0.f);
        o.z = fmaxf((hv.z - m4.z) * (g4.z * rsqrtf(v4.z + EPS_BN)) + b4.z, 0.f);
        o.w = fmaxf((hv.w - m4.w) * (g4.w * rsqrtf(v4.w + EPS_BN)) + b4.w, 0.f);
        reinterpret_cast<float4*>(r)[k] = o;
    }
}

// ---------------------------------------------------------------------------
// SGEMM: C[M,N] = A[M,K] @ B[K,N] (+bias) with fused epilogues.
//   EPI 0: C = acc + bias
//   EPI 1: C = relu(bn(acc + bias))     (BN params per column)
//   EPI 2: C += acc + bias              (residual accumulate)
// 128x128 tile, BK=8, 256 threads, 8x8 per thread.
// ---------------------------------------------------------------------------
template<int EPI>
__global__ __launch_bounds__(256)
void sgemm_kernel(const float* __restrict__ A, const float* __restrict__ B,
                  const float* __restrict__ bias, float* __restrict__ C,
                  int M, int N, int K,
                  const float* __restrict__ bng, const float* __restrict__ bnb,
                  const float* __restrict__ bnm, const float* __restrict__ bnv)
{
    __shared__ float As[8][128];
    __shared__ float Bs[8][128];

    int tid = threadIdx.x;
    int tx = tid & 15;       // 0..15 -> 8 cols each
    int ty = tid >> 4;       // 0..15 -> 8 rows each
    int rowBase = blockIdx.x * 128;
    int colBase = blockIdx.y * 128;

    int aRow = tid >> 1;           // 0..127
    int aCol = (tid & 1) * 4;      // 0 or 4
    int bRow = tid >> 5;           // 0..7
    int bCol = (tid & 31) * 4;     // 0..124

    float acc[8][8];
#pragma unroll
    for (int i = 0; i < 8; i++)
#pragma unroll
        for (int j = 0; j < 8; j++) acc[i][j] = 0.f;

    int gArow = rowBase + aRow;
    bool aValid = (gArow < M);
    const float* Aptr = A + (long)gArow * K + aCol;
    const float* Bptr = B + (long)bRow * N + colBase + bCol;

    for (int k0 = 0; k0 < K; k0 += 8) {
        float4 av = aValid ? *reinterpret_cast<const float4*>(Aptr + k0)
                           : make_float4(0.f, 0.f, 0.f, 0.f);
        float4 bv = *reinterpret_cast<const float4*>(Bptr + (long)k0 * N);
        As[aCol + 0][aRow] = av.x;
        As[aCol + 1][aRow] = av.y;
        As[aCol + 2][aRow] = av.z;
        As[aCol + 3][aRow] = av.w;
        *reinterpret_cast<float4*>(&Bs[bRow][bCol]) = bv;
        __syncthreads();

#pragma unroll
        for (int k = 0; k < 8; k++) {
            float a[8], b[8];
            *reinterpret_cast<float4*>(a)     = *reinterpret_cast<float4*>(&As[k][ty * 8]);
            *reinterpret_cast<float4*>(a + 4) = *reinterpret_cast<float4*>(&As[k][ty * 8 + 4]);
            *reinterpret_cast<float4*>(b)     = *reinterpret_cast<float4*>(&Bs[k][tx * 8]);
            *reinterpret_cast<float4*>(b + 4) = *reinterpret_cast<float4*>(&Bs[k][tx * 8 + 4]);
#pragma unroll
            for (int i = 0; i < 8; i++)
#pragma unroll
                for (int j = 0; j < 8; j++)
                    acc[i][j] = fmaf(a[i], b[j], acc[i][j]);
        }
        __syncthreads();
    }

#pragma unroll
    for (int j = 0; j < 8; j++) {
        int col = colBase + tx * 8 + j;
        float bi = bias[col];
        float sc = 1.f, sh = 0.f;
        if (EPI == 1) {
            sc = bng[col] * rsqrtf(bnv[col] + EPS_BN);
            sh = bnb[col] - bnm[col] * sc;
        }
#pragma unroll
        for (int i = 0; i < 8; i++) {
            int row = rowBase + ty * 8 + i;
            if (row < M) {
                float val = acc[i][j] + bi;
                long idx = (long)row * N + col;
                if (EPI == 0)      C[idx] = val;
                else if (EPI == 1) C[idx] = fmaxf(fmaf(val, sc, sh), 0.f);
                else               C[idx] += val;
            }
        }
    }
}

// ---------------------------------------------------------------------------
// Final: f = relu(bn0(h)); pooled[batch] += f ; cnt[batch] += 1
// ---------------------------------------------------------------------------
__global__ void pool_kernel(const int* __restrict__ batch,
                            const float* __restrict__ gg,
                            const float* __restrict__ gb,
                            const float* __restrict__ gm,
                            const float* __restrict__ gv)
{
    int node = blockIdx.x;
    int c = threadIdx.x;
    int bg = batch[node];
    float hv = g_h[(long)node * H + c];
    float sc = gg[c] * rsqrtf(gv[c] + EPS_BN);
    float val = fmaxf((hv - gm[c]) * sc + gb[c], 0.f);
    atomicAdd(&g_pool[bg * H + c], val);
    if (c == 0) atomicAdd(&g_cnt[bg], 1.f);
}

// ---------------------------------------------------------------------------
// Classifier: out[g, c] = [pooled/cnt, clinical] @ cls_w + cls_b
// ---------------------------------------------------------------------------
__global__ void cls_kernel(const float* __restrict__ clinical,
                           const float* __restrict__ cw,
                           const float* __restrict__ cb,
                           float* __restrict__ out)
{
    int tid = threadIdx.x;
    if (tid >= NGRAPH * NCLS) return;
    int g = tid >> 1;
    int c = tid & 1;
    float inv = 1.f / fmaxf(g_cnt[g], 1.f);
    float acc = cb[c];
    for (int j = 0; j < H; j++)
        acc += g_pool[g * H + j] * inv * cw[j * NCLS + c];
    for (int k = 0; k < KCLIN; k++)
        acc += clinical[g * KCLIN + k] * cw[(H + k) * NCLS + c];
    out[g * NCLS + c] = acc;
}

// ---------------------------------------------------------------------------
extern "C" void kernel_launch(void* const* d_in, const int* in_sizes, int n_in,
                              void* d_out, int out_size)
{
    const float* x        = (const float*)d_in[0];
    const int*   ei       = (const int*)  d_in[1];
    const float* eattr    = (const float*)d_in[2];
    const int*   batch    = (const int*)  d_in[3];
    const float* clinical = (const float*)d_in[4];
    const float* lsw = (const float*)d_in[5],  *lsb = (const float*)d_in[6];
    const float* ldw = (const float*)d_in[7],  *ldb = (const float*)d_in[8];
    const float* ew  = (const float*)d_in[9],  *ebp = (const float*)d_in[10];
    const float* t   = (const float*)d_in[11];
    const float* w1  = (const float*)d_in[12], *b1  = (const float*)d_in[13];
    const float* bg  = (const float*)d_in[14], *bb  = (const float*)d_in[15];
    const float* bm  = (const float*)d_in[16], *bv  = (const float*)d_in[17];
    const float* w2  = (const float*)d_in[18], *b2  = (const float*)d_in[19];
    const float* ng  = (const float*)d_in[20], *nb  = (const float*)d_in[21];
    const float* nm  = (const float*)d_in[22], *nv  = (const float*)d_in[23];
    const float* cw  = (const float*)d_in[24], *cb  = (const float*)d_in[25];
    float* out = (float*)d_out;

    const int* src = ei;
    const int* dstp = ei + N_EDGES;

    float *xs, *xd, *hbuf, *obuf, *mid;
    cudaGetSymbolAddress((void**)&xs,   g_xs);
    cudaGetSymbolAddress((void**)&xd,   g_xd);
    cudaGetSymbolAddress((void**)&hbuf, g_h);
    cudaGetSymbolAddress((void**)&obuf, g_out);
    cudaGetSymbolAddress((void**)&mid,  g_mid);

    zero_kernel<<<512, 256>>>();

    dim3 grid1((N_NODES + 127) / 128, 1);
    dim3 grid2((N_NODES + 127) / 128, 2);

    // Input projections: xs0 = x@lin_src_w + b ; xd0 = x@lin_dst_w + b
    sgemm_kernel<0><<<grid1, 256>>>(x, lsw, lsb, xs, N_NODES, H, C_IN,
                                    nullptr, nullptr, nullptr, nullptr);
    sgemm_kernel<0><<<grid1, 256>>>(x, ldw, ldb, xd, N_NODES, H, C_IN,
                                    nullptr, nullptr, nullptr, nullptr);

    for (int l = 0; l < NLAYERS; l++) {
        const float* xsl;
        const float* xdl;
        if (l == 0) {
            xsl = xs; xdl = xd;
        } else {
            relubn_kernel<<<512, 256>>>(hbuf, ng + l * H, nb + l * H,
                                        nm + l * H, nv + l * H, xs);
            xsl = xs; xdl = xs;
        }
        edge_kernel<<<4096, 256>>>(src, dstp, eattr, xsl,
                                   ew + l * H, ebp + l * H, t, l);
        agg_kernel<<<512, 256>>>(xdl);

        // mid = relu(bn(out @ w1 + b1))   [N, 2H]
        sgemm_kernel<1><<<grid2, 256>>>(obuf, w1 + (long)l * H * H2, b1 + l * H2,
                                        mid, N_NODES, H2, H,
                                        bg + l * H2, bb + l * H2,
                                        bm + l * H2, bv + l * H2);
        // conv = mid @ w2 + b2 ; h = conv (l==0) or h += conv
        if (l == 0)
            sgemm_kernel<0><<<grid1, 256>>>(mid, w2 + (long)l * H2 * H, b2 + l * H,
                                            hbuf, N_NODES, H, H2,
                                            nullptr, nullptr, nullptr, nullptr);
        else
            sgemm_kernel<2><<<grid1, 256>>>(mid, w2 + (long)l * H2 * H, b2 + l * H,
                                            hbuf, N_NODES, H, H2,
                                            nullptr, nullptr, nullptr, nullptr);
    }

    pool_kernel<<<N_NODES, H>>>(batch, ng, nb, nm, nv);
    cls_kernel<<<1, 128>>>(clinical, cw, cb, out);
}

// round 2
// speedup vs baseline: 1.0651x; 1.0651x over previous
#include <cuda_runtime.h>
#include <math.h>

// Problem dims (fixed by dataset)
#define N_NODES 50000
#define N_EDGES 500000
#define C_IN    256
#define H       128
#define H2      256
#define NLAYERS 4
#define NGRAPH  64
#define KCLIN   8
#define NCLS    2
#define EPS_MSG 1e-7f
#define EPS_BN  1e-5f

#define SCAN_B  512
#define SCAN_NB ((N_NODES + SCAN_B - 1) / SCAN_B)   // 98

// Scratch (device globals; no allocation allowed)
__device__ float g_xs  [N_NODES * H];
__device__ float g_xd  [N_NODES * H];
__device__ float g_h   [N_NODES * H];
__device__ float g_out [N_NODES * H];
__device__ float g_mid [N_NODES * H2];
__device__ float g_pool[NGRAPH * H];
__device__ float g_cnt [NGRAPH];

// CSR build scratch
__device__ int  g_count[N_NODES];       // histogram, then scatter cursor
__device__ int  g_row  [N_NODES + 1];
__device__ int  g_bsum [128];
__device__ int2 g_edges[N_EDGES];       // .x = src id, .y = bits of eattr

// ---------------------------------------------------------------------------
__global__ void zero_kernel() {
    int i = blockIdx.x * blockDim.x + threadIdx.x;
    int stride = gridDim.x * blockDim.x;
    for (int k = i; k < N_NODES; k += stride) g_count[k] = 0;
    if (i < NGRAPH * H) g_pool[i] = 0.f;
    if (i < NGRAPH) g_cnt[i] = 0.f;
}

// ---------------------------------------------------------------------------
// CSR build: histogram -> 2-level exclusive scan -> scatter
// ---------------------------------------------------------------------------
__global__ void hist_kernel(const int* __restrict__ dst) {
    int i = blockIdx.x * blockDim.x + threadIdx.x;
    if (i < N_EDGES) atomicAdd(&g_count[dst[i]], 1);
}

__global__ void scan_local_kernel() {
    __shared__ int sh[SCAN_B];
    int tid = threadIdx.x;
    int i = blockIdx.x * SCAN_B + tid;
    int v = (i < N_NODES) ? g_count[i] : 0;
    sh[tid] = v;
    __syncthreads();
    for (int off = 1; off < SCAN_B; off <<= 1) {
        int t = (tid >= off) ? sh[tid - off] : 0;
        __syncthreads();
        sh[tid] += t;
        __syncthreads();
    }
    if (i < N_NODES) g_row[i] = sh[tid] - v;            // exclusive within block
    if (tid == SCAN_B - 1) g_bsum[blockIdx.x] = sh[tid]; // block total
}

__global__ void scan_bsum_kernel() {
    __shared__ int sh[128];
    int tid = threadIdx.x;
    int v = (tid < SCAN_NB) ? g_bsum[tid] : 0;
    sh[tid] = v;
    __syncthreads();
    for (int off = 1; off < 128; off <<= 1) {
        int t = (tid >= off) ? sh[tid - off] : 0;
        __syncthreads();
        sh[tid] += t;
        __syncthreads();
    }
    if (tid < SCAN_NB) g_bsum[tid] = sh[tid] - v;       // exclusive
}

__global__ void scan_add_kernel() {
    int i = blockIdx.x * blockDim.x + threadIdx.x;
    if (i < N_NODES) {
        int r = g_row[i] + g_bsum[i / SCAN_B];
        g_row[i] = r;
        g_count[i] = r;                                  // cursor for scatter
    }
    if (i == 0) g_row[N_NODES] = N_EDGES;
}

__global__ void scatter_kernel(const int* __restrict__ src,
                               const int* __restrict__ dst,
                               const float* __restrict__ eattr) {
    int e = blockIdx.x * blockDim.x + threadIdx.x;
    if (e >= N_EDGES) return;
    int d = dst[e];
    int pos = atomicAdd(&g_count[d], 1);
    g_edges[pos] = make_int2(src[e], __float_as_int(eattr[e]));
}

// ---------------------------------------------------------------------------
// Gather: one warp per dst node. Softmax aggregation without max-shift
// (exp(z - zmax) cancels between num and denom; z is small so exp(z) is safe).
// Writes out = num/den + xd directly; no atomics, no num/den buffers.
// ---------------------------------------------------------------------------
__global__ __launch_bounds__(256)
void gather_kernel(const float* __restrict__ xs,
                   const float* __restrict__ xd,
                   const float* __restrict__ ew,
                   const float* __restrict__ eb,
                   const float* __restrict__ tptr, int l,
                   float* __restrict__ out)
{
    int warp = (blockIdx.x * blockDim.x + threadIdx.x) >> 5;
    if (warp >= N_NODES) return;
    int lane = threadIdx.x & 31;
    int c0 = lane * 4;

    float4 w4 = *reinterpret_cast<const float4*>(ew + c0);
    float4 b4 = *reinterpret_cast<const float4*>(eb + c0);
    float tv = tptr[l];

    int e0 = g_row[warp];
    int e1 = g_row[warp + 1];

    float n0 = 0.f, n1 = 0.f, n2 = 0.f, n3 = 0.f;
    float d0 = 0.f, d1 = 0.f, d2 = 0.f, d3 = 0.f;

#pragma unroll 2
    for (int e = e0; e < e1; e++) {
        int2 ed = g_edges[e];              // broadcast 8B load
        int   s  = ed.x;
        float al = __int_as_float(ed.y);
        float4 x4 = *reinterpret_cast<const float4*>(xs + (long)s * H + c0);

        float m0 = fmaxf(fmaf(al, w4.x, b4.x) + x4.x, 0.f) + EPS_MSG;
        float m1 = fmaxf(fmaf(al, w4.y, b4.y) + x4.y, 0.f) + EPS_MSG;
        float m2 = fmaxf(fmaf(al, w4.z, b4.z) + x4.z, 0.f) + EPS_MSG;
        float m3 = fmaxf(fmaf(al, w4.w, b4.w) + x4.w, 0.f) + EPS_MSG;

        float z0 = __expf(m0 * tv);
        float z1 = __expf(m1 * tv);
        float z2 = __expf(m2 * tv);
        float z3 = __expf(m3 * tv);

        d0 += z0; d1 += z1; d2 += z2; d3 += z3;
        n0 = fmaf(m0, z0, n0); n1 = fmaf(m1, z1, n1);
        n2 = fmaf(m2, z2, n2); n3 = fmaf(m3, z3, n3);
    }

    float4 xv = *reinterpret_cast<const float4*>(xd + (long)warp * H + c0);
    float4 o;
    o.x = n0 / fmaxf(d0, 1e-16f) + xv.x;
    o.y = n1 / fmaxf(d1, 1e-16f) + xv.y;
    o.z = n2 / fmaxf(d2, 1e-16f) + xv.z;
    o.w = n3 / fmaxf(d3, 1e-16f) + xv.w;
    *reinterpret_cast<float4*>(out + (long)warp * H + c0) = o;
}

// ---------------------------------------------------------------------------
// r = relu(batchnorm(h)) elementwise
// ---------------------------------------------------------------------------
__global__ void relubn_kernel(const float* __restrict__ h,
                              const float* __restrict__ gg,
                              const float* __restrict__ gb,
                              const float* __restrict__ gm,
                              const float* __restrict__ gv,
                              float* __restrict__ r)
{
    int i = blockIdx.x * blockDim.x + threadIdx.x;
    int stride = gridDim.x * blockDim.x;
    const int n4 = N_NODES * H / 4;
    for (int k = i; k < n4; k += stride) {
        int c0 = (k * 4) & (H - 1);
        float4 hv = reinterpret_cast<const float4*>(h)[k];
        float4 g4 = *reinterpret_cast<const float4*>(gg + c0);
        float4 b4 = *reinterpret_cast<const float4*>(gb + c0);
        float4 m4 = *reinterpret_cast<const float4*>(gm + c0);
        float4 v4 = *reinterpret_cast<const float4*>(gv + c0);
        float4 o;
        o.x = fmaxf((hv.x - m4.x) * (g4.x * rsqrtf(v4.x + EPS_BN)) + b4.x, 0.f);
        o.y = fmaxf((hv.y - m4.y) * (g4.y * rsqrtf(v4.y + EPS_BN)) + b4.y, 0.f);
        o.z = fmaxf((hv.z - m4.z) * (g4.z * rsqrtf(v4.z + EPS_BN)) + b4.z, 0.f);
        o.w = fmaxf((hv.w - m4.w) * (g4.w * rsqrtf(v4.w + EPS_BN)) + b4.w, 0.f);
        reinterpret_cast<float4*>(r)[k] = o;
    }
}

// ---------------------------------------------------------------------------
// SGEMM with packed fma.rn.f32x2 inner product (2 FLOPs per FFMA2 issue).
//   EPI 0: C = acc + bias
//   EPI 1: C = relu(bn(acc + bias))
//   EPI 2: C += acc + bias
// 128x128 tile, BK=8, 256 threads, 8x8 per thread.
// ---------------------------------------------------------------------------
__device__ __forceinline__ unsigned long long pack_f2(float x) {
    unsigned long long r;
    asm("mov.b64 %0, {%1, %1};" : "=l"(r) : "f"(x));
    return r;
}
__device__ __forceinline__ void ffma2(unsigned long long& acc,
                                      unsigned long long a2,
                                      unsigned long long b2) {
    asm("fma.rn.f32x2 %0, %1, %2, %0;" : "+l"(acc) : "l"(a2), "l"(b2));
}
__device__ __forceinline__ void unpack_f2(unsigned long long v, float& lo, float& hi) {
    asm("mov.b64 {%0, %1}, %2;" : "=f"(lo), "=f"(hi) : "l"(v));
}

template<int EPI>
__global__ __launch_bounds__(256)
void sgemm_kernel(const float* __restrict__ A, const float* __restrict__ B,
                  const float* __restrict__ bias, float* __restrict__ C,
                  int M, int N, int K,
                  const float* __restrict__ bng, const float* __restrict__ bnb,
                  const float* __restrict__ bnm, const float* __restrict__ bnv)
{
    __shared__ float As[8][128];
    __shared__ float Bs[8][128];

    int tid = threadIdx.x;
    int tx = tid & 15;       // 8 cols each
    int ty = tid >> 4;       // 8 rows each
    int rowBase = blockIdx.x * 128;
    int colBase = blockIdx.y * 128;

    int aRow = tid >> 1;
    int aCol = (tid & 1) * 4;
    int bRow = tid >> 5;
    int bCol = (tid & 31) * 4;

    unsigned long long acc2[8][4];
#pragma unroll
    for (int i = 0; i < 8; i++)
#pragma unroll
        for (int j = 0; j < 4; j++) acc2[i][j] = 0ull;

    int gArow = rowBase + aRow;
    bool aValid = (gArow < M);
    const float* Aptr = A + (long)gArow * K + aCol;
    const float* Bptr = B + (long)bRow * N + colBase + bCol;

    for (int k0 = 0; k0 < K; k0 += 8) {
        float4 av = aValid ? *reinterpret_cast<const float4*>(Aptr + k0)
                           : make_float4(0.f, 0.f, 0.f, 0.f);
        float4 bv = *reinterpret_cast<const float4*>(Bptr + (long)k0 * N);
        As[aCol + 0][aRow] = av.x;
        As[aCol + 1][aRow] = av.y;
        As[aCol + 2][aRow] = av.z;
        As[aCol + 3][aRow] = av.w;
        *reinterpret_cast<float4*>(&Bs[bRow][bCol]) = bv;
        __syncthreads();

#pragma unroll
        for (int k = 0; k < 8; k++) {
            float a[8];
            *reinterpret_cast<float4*>(a)     = *reinterpret_cast<float4*>(&As[k][ty * 8]);
            *reinterpret_cast<float4*>(a + 4) = *reinterpret_cast<float4*>(&As[k][ty * 8 + 4]);
            unsigned long long b2[4];
            const unsigned long long* bp =
                reinterpret_cast<const unsigned long long*>(&Bs[k][tx * 8]);
            b2[0] = bp[0]; b2[1] = bp[1]; b2[2] = bp[2]; b2[3] = bp[3];
#pragma unroll
            for (int i = 0; i < 8; i++) {
                unsigned long long a2 = pack_f2(a[i]);
#pragma unroll
                for (int j = 0; j < 4; j++) ffma2(acc2[i][j], a2, b2[j]);
            }
        }
        __syncthreads();
    }

#pragma unroll
    for (int j2 = 0; j2 < 4; j2++) {
        int colL = colBase + tx * 8 + j2 * 2;
        float biL = bias[colL], biH = bias[colL + 1];
        float scL = 1.f, shL = 0.f, scH = 1.f, shH = 0.f;
        if (EPI == 1) {
            scL = bng[colL] * rsqrtf(bnv[colL] + EPS_BN);
            shL = bnb[colL] - bnm[colL] * scL;
            scH = bng[colL + 1] * rsqrtf(bnv[colL + 1] + EPS_BN);
            shH = bnb[colL + 1] - bnm[colL + 1] * scH;
        }
#pragma unroll
        for (int i = 0; i < 8; i++) {
            int row = rowBase + ty * 8 + i;
            if (row < M) {
                float lo, hi;
                unpack_f2(acc2[i][j2], lo, hi);
                float vL = lo + biL;
                float vH = hi + biH;
                long idx = (long)row * N + colL;
                if (EPI == 0) {
                    C[idx] = vL; C[idx + 1] = vH;
                } else if (EPI == 1) {
                    C[idx]     = fmaxf(fmaf(vL, scL, shL), 0.f);
                    C[idx + 1] = fmaxf(fmaf(vH, scH, shH), 0.f);
                } else {
                    C[idx] += vL; C[idx + 1] += vH;
                }
            }
        }
    }
}

// ---------------------------------------------------------------------------
__global__ void pool_kernel(const int* __restrict__ batch,
                            const float* __restrict__ gg,
                            const float* __restrict__ gb,
                            const float* __restrict__ gm,
                            const float* __restrict__ gv)
{
    int node = blockIdx.x;
    int c = threadIdx.x;
    int bg = batch[node];
    float hv = g_h[(long)node * H + c];
    float sc = gg[c] * rsqrtf(gv[c] + EPS_BN);
    float val = fmaxf((hv - gm[c]) * sc + gb[c], 0.f);
    atomicAdd(&g_pool[bg * H + c], val);
    if (c == 0) atomicAdd(&g_cnt[bg], 1.f);
}

__global__ void cls_kernel(const float* __restrict__ clinical,
                           const float* __restrict__ cw,
                           const float* __restrict__ cb,
                           float* __restrict__ out)
{
    int tid = threadIdx.x;
    if (tid >= NGRAPH * NCLS) return;
    int g = tid >> 1;
    int c = tid & 1;
    float inv = 1.f / fmaxf(g_cnt[g], 1.f);
    float acc = cb[c];
    for (int j = 0; j < H; j++)
        acc += g_pool[g * H + j] * inv * cw[j * NCLS + c];
    for (int k = 0; k < KCLIN; k++)
        acc += clinical[g * KCLIN + k] * cw[(H + k) * NCLS + c];
    out[g * NCLS + c] = acc;
}

// ---------------------------------------------------------------------------
extern "C" void kernel_launch(void* const* d_in, const int* in_sizes, int n_in,
                              void* d_out, int out_size)
{
    const float* x        = (const float*)d_in[0];
    const int*   ei       = (const int*)  d_in[1];
    const float* eattr    = (const float*)d_in[2];
    const int*   batch    = (const int*)  d_in[3];
    const float* clinical = (const float*)d_in[4];
    const float* lsw = (const float*)d_in[5],  *lsb = (const float*)d_in[6];
    const float* ldw = (const float*)d_in[7],  *ldb = (const float*)d_in[8];
    const float* ew  = (const float*)d_in[9],  *ebp = (const float*)d_in[10];
    const float* t   = (const float*)d_in[11];
    const float* w1  = (const float*)d_in[12], *b1  = (const float*)d_in[13];
    const float* bg  = (const float*)d_in[14], *bb  = (const float*)d_in[15];
    const float* bm  = (const float*)d_in[16], *bv  = (const float*)d_in[17];
    const float* w2  = (const float*)d_in[18], *b2  = (const float*)d_in[19];
    const float* ng  = (const float*)d_in[20], *nb  = (const float*)d_in[21];
    const float* nm  = (const float*)d_in[22], *nv  = (const float*)d_in[23];
    const float* cw  = (const float*)d_in[24], *cb  = (const float*)d_in[25];
    float* out = (float*)d_out;

    const int* src = ei;
    const int* dstp = ei + N_EDGES;

    float *xs, *xd, *hbuf, *obuf, *mid;
    cudaGetSymbolAddress((void**)&xs,   g_xs);
    cudaGetSymbolAddress((void**)&xd,   g_xd);
    cudaGetSymbolAddress((void**)&hbuf, g_h);
    cudaGetSymbolAddress((void**)&obuf, g_out);
    cudaGetSymbolAddress((void**)&mid,  g_mid);

    // CSR build (once per launch; edge structure is layer-invariant)
    zero_kernel<<<256, 256>>>();
    hist_kernel<<<(N_EDGES + 255) / 256, 256>>>(dstp);
    scan_local_kernel<<<SCAN_NB, SCAN_B>>>();
    scan_bsum_kernel<<<1, 128>>>();
    scan_add_kernel<<<(N_NODES + 255) / 256, 256>>>();
    scatter_kernel<<<(N_EDGES + 255) / 256, 256>>>(src, dstp, eattr);

    dim3 grid1((N_NODES + 127) / 128, 1);
    dim3 grid2((N_NODES + 127) / 128, 2);

    sgemm_kernel<0><<<grid1, 256>>>(x, lsw, lsb, xs, N_NODES, H, C_IN,
                                    nullptr, nullptr, nullptr, nullptr);
    sgemm_kernel<0><<<grid1, 256>>>(x, ldw, ldb, xd, N_NODES, H, C_IN,
                                    nullptr, nullptr, nullptr, nullptr);

    for (int l = 0; l < NLAYERS; l++) {
        const float* xsl;
        const float* xdl;
        if (l == 0) {
            xsl = xs; xdl = xd;
        } else {
            relubn_kernel<<<512, 256>>>(hbuf, ng + l * H, nb + l * H,
                                        nm + l * H, nv + l * H, xs);
            xsl = xs; xdl = xs;
        }
        gather_kernel<<<(N_NODES * 32 + 255) / 256, 256>>>(
            xsl, xdl, ew + l * H, ebp + l * H, t, l, obuf);

        sgemm_kernel<1><<<grid2, 256>>>(obuf, w1 + (long)l * H * H2, b1 + l * H2,
                                        mid, N_NODES, H2, H,
                                        bg + l * H2, bb + l * H2,
                                        bm + l * H2, bv + l * H2);
        if (l == 0)
            sgemm_kernel<0><<<grid1, 256>>>(mid, w2 + (long)l * H2 * H, b2 + l * H,
                                            hbuf, N_NODES, H, H2,
                                            nullptr, nullptr, nullptr, nullptr);
        else
            sgemm_kernel<2><<<grid1, 256>>>(mid, w2 + (long)l * H2 * H, b2 + l * H,
                                            hbuf, N_NODES, H, H2,
                                            nullptr, nullptr, nullptr, nullptr);
    }

    pool_kernel<<<N_NODES, H>>>(batch, ng, nb, nm, nv);
    cls_kernel<<<1, 128>>>(clinical, cw, cb, out);
}

// round 3
// speedup vs baseline: 2.6844x; 2.5203x over previous
#include <cuda_runtime.h>
#include <math.h>

// Problem dims (fixed by dataset)
#define N_NODES 50000
#define N_EDGES 500000
#define C_IN    256
#define H       128
#define H2      256
#define NLAYERS 4
#define NGRAPH  64
#define KCLIN   8
#define NCLS    2
#define EPS_MSG 1e-7f
#define EPS_BN  1e-5f

#define SCAN_B  512
#define SCAN_NB ((N_NODES + SCAN_B - 1) / SCAN_B)   // 98

// Scratch (device globals; no allocation allowed)
__device__ float g_xs  [N_NODES * H];
__device__ float g_xd  [N_NODES * H];
__device__ float g_h   [N_NODES * H];
__device__ float g_out [N_NODES * H];
__device__ float g_mid [N_NODES * H2];
__device__ float g_pool[NGRAPH * H];
__device__ float g_cnt [NGRAPH];

// CSR build scratch
__device__ int  g_count[N_NODES];
__device__ int  g_row  [N_NODES + 1];
__device__ int  g_bsum [128];
__device__ int2 g_edges[N_EDGES];       // .x = src id, .y = bits of eattr

// ---------------------------------------------------------------------------
__global__ void zero_kernel() {
    int i = blockIdx.x * blockDim.x + threadIdx.x;
    int stride = gridDim.x * blockDim.x;
    for (int k = i; k < N_NODES; k += stride) g_count[k] = 0;
    if (i < NGRAPH * H) g_pool[i] = 0.f;
    if (i < NGRAPH) g_cnt[i] = 0.f;
}

// ---------------------------------------------------------------------------
// CSR build: histogram -> 2-level exclusive scan -> scatter
// ---------------------------------------------------------------------------
__global__ void hist_kernel(const int* __restrict__ dst) {
    int i = blockIdx.x * blockDim.x + threadIdx.x;
    if (i < N_EDGES) atomicAdd(&g_count[dst[i]], 1);
}

__global__ void scan_local_kernel() {
    __shared__ int sh[SCAN_B];
    int tid = threadIdx.x;
    int i = blockIdx.x * SCAN_B + tid;
    int v = (i < N_NODES) ? g_count[i] : 0;
    sh[tid] = v;
    __syncthreads();
    for (int off = 1; off < SCAN_B; off <<= 1) {
        int t = (tid >= off) ? sh[tid - off] : 0;
        __syncthreads();
        sh[tid] += t;
        __syncthreads();
    }
    if (i < N_NODES) g_row[i] = sh[tid] - v;
    if (tid == SCAN_B - 1) g_bsum[blockIdx.x] = sh[tid];
}

__global__ void scan_bsum_kernel() {
    __shared__ int sh[128];
    int tid = threadIdx.x;
    int v = (tid < SCAN_NB) ? g_bsum[tid] : 0;
    sh[tid] = v;
    __syncthreads();
    for (int off = 1; off < 128; off <<= 1) {
        int t = (tid >= off) ? sh[tid - off] : 0;
        __syncthreads();
        sh[tid] += t;
        __syncthreads();
    }
    if (tid < SCAN_NB) g_bsum[tid] = sh[tid] - v;
}

__global__ void scan_add_kernel() {
    int i = blockIdx.x * blockDim.x + threadIdx.x;
    if (i < N_NODES) {
        int r = g_row[i] + g_bsum[i / SCAN_B];
        g_row[i] = r;
        g_count[i] = r;
    }
    if (i == 0) g_row[N_NODES] = N_EDGES;
}

__global__ void scatter_kernel(const int* __restrict__ src,
                               const int* __restrict__ dst,
                               const float* __restrict__ eattr) {
    int e = blockIdx.x * blockDim.x + threadIdx.x;
    if (e >= N_EDGES) return;
    int d = dst[e];
    int pos = atomicAdd(&g_count[d], 1);
    g_edges[pos] = make_int2(src[e], __float_as_int(eattr[e]));
}

// ---------------------------------------------------------------------------
// Gather: one warp per dst node, softmax aggregation without max-shift.
// ---------------------------------------------------------------------------
__global__ __launch_bounds__(256)
void gather_kernel(const float* __restrict__ xs,
                   const float* __restrict__ xd,
                   const float* __restrict__ ew,
                   const float* __restrict__ eb,
                   const float* __restrict__ tptr, int l,
                   float* __restrict__ out)
{
    int warp = (blockIdx.x * blockDim.x + threadIdx.x) >> 5;
    if (warp >= N_NODES) return;
    int lane = threadIdx.x & 31;
    int c0 = lane * 4;

    float4 w4 = *reinterpret_cast<const float4*>(ew + c0);
    float4 b4 = *reinterpret_cast<const float4*>(eb + c0);
    float tv = tptr[l];

    int e0 = g_row[warp];
    int e1 = g_row[warp + 1];

    float n0 = 0.f, n1 = 0.f, n2 = 0.f, n3 = 0.f;
    float d0 = 0.f, d1 = 0.f, d2 = 0.f, d3 = 0.f;

#pragma unroll 2
    for (int e = e0; e < e1; e++) {
        int2 ed = g_edges[e];
        int   s  = ed.x;
        float al = __int_as_float(ed.y);
        float4 x4 = *reinterpret_cast<const float4*>(xs + (long)s * H + c0);

        float m0 = fmaxf(fmaf(al, w4.x, b4.x) + x4.x, 0.f) + EPS_MSG;
        float m1 = fmaxf(fmaf(al, w4.y, b4.y) + x4.y, 0.f) + EPS_MSG;
        float m2 = fmaxf(fmaf(al, w4.z, b4.z) + x4.z, 0.f) + EPS_MSG;
        float m3 = fmaxf(fmaf(al, w4.w, b4.w) + x4.w, 0.f) + EPS_MSG;

        float z0 = __expf(m0 * tv);
        float z1 = __expf(m1 * tv);
        float z2 = __expf(m2 * tv);
        float z3 = __expf(m3 * tv);

        d0 += z0; d1 += z1; d2 += z2; d3 += z3;
        n0 = fmaf(m0, z0, n0); n1 = fmaf(m1, z1, n1);
        n2 = fmaf(m2, z2, n2); n3 = fmaf(m3, z3, n3);
    }

    float4 xv = *reinterpret_cast<const float4*>(xd + (long)warp * H + c0);
    float4 o;
    o.x = n0 / fmaxf(d0, 1e-16f) + xv.x;
    o.y = n1 / fmaxf(d1, 1e-16f) + xv.y;
    o.z = n2 / fmaxf(d2, 1e-16f) + xv.z;
    o.w = n3 / fmaxf(d3, 1e-16f) + xv.w;
    *reinterpret_cast<float4*>(out + (long)warp * H + c0) = o;
}

// ---------------------------------------------------------------------------
__global__ void relubn_kernel(const float* __restrict__ h,
                              const float* __restrict__ gg,
                              const float* __restrict__ gb,
                              const float* __restrict__ gm,
                              const float* __restrict__ gv,
                              float* __restrict__ r)
{
    int i = blockIdx.x * blockDim.x + threadIdx.x;
    int stride = gridDim.x * blockDim.x;
    const int n4 = N_NODES * H / 4;
    for (int k = i; k < n4; k += stride) {
        int c0 = (k * 4) & (H - 1);
        float4 hv = reinterpret_cast<const float4*>(h)[k];
        float4 g4 = *reinterpret_cast<const float4*>(gg + c0);
        float4 b4 = *reinterpret_cast<const float4*>(gb + c0);
        float4 m4 = *reinterpret_cast<const float4*>(gm + c0);
        float4 v4 = *reinterpret_cast<const float4*>(gv + c0);
        float4 o;
        o.x = fmaxf((hv.x - m4.x) * (g4.x * rsqrtf(v4.x + EPS_BN)) + b4.x, 0.f);
        o.y = fmaxf((hv.y - m4.y) * (g4.y * rsqrtf(v4.y + EPS_BN)) + b4.y, 0.f);
        o.z = fmaxf((hv.z - m4.z) * (g4.z * rsqrtf(v4.z + EPS_BN)) + b4.z, 0.f);
        o.w = fmaxf((hv.w - m4.w) * (g4.w * rsqrtf(v4.w + EPS_BN)) + b4.w, 0.f);
        reinterpret_cast<float4*>(r)[k] = o;
    }
}

// ---------------------------------------------------------------------------
// Tensor-core GEMM: tf32x3 split (Ah*Bh + Ah*Bl + Al*Bh) ~ fp32 accuracy.
// C[M,N] = A[M,K] @ B[K,N] + bias, with fused epilogues:
//   EPI 0: C = acc + bias
//   EPI 1: C = relu(bn(acc + bias))
//   EPI 2: C += acc + bias
// 128x128 tile, BK=16, 256 threads (8 warps, 2x4), warp tile 64x32.
// smem [k][m] / [k][n] stride 136 (mod 32 == 8 -> conflict-free frag LDS).
// ---------------------------------------------------------------------------
__device__ __forceinline__ unsigned f2tf(float f) {
    unsigned r;
    asm("cvt.rna.tf32.f32 %0, %1;" : "=r"(r) : "f"(f));
    return r;
}
__device__ __forceinline__ void split_tf32(float v, unsigned& hi, unsigned& lo) {
    hi = f2tf(v);
    lo = f2tf(v - __uint_as_float(hi));
}
__device__ __forceinline__ void mma_tf32(float c[4],
                                         unsigned a0, unsigned a1, unsigned a2, unsigned a3,
                                         unsigned b0, unsigned b1) {
    asm volatile(
        "mma.sync.aligned.m16n8k8.row.col.f32.tf32.tf32.f32 "
        "{%0,%1,%2,%3}, {%4,%5,%6,%7}, {%8,%9}, {%0,%1,%2,%3};"
        : "+f"(c[0]), "+f"(c[1]), "+f"(c[2]), "+f"(c[3])
        : "r"(a0), "r"(a1), "r"(a2), "r"(a3), "r"(b0), "r"(b1));
}

#define SMS 136   // smem row stride in words

template<int EPI>
__global__ __launch_bounds__(256)
void tgemm_kernel(const float* __restrict__ A, const float* __restrict__ B,
                  const float* __restrict__ bias, float* __restrict__ C,
                  int M, int N, int K,
                  const float* __restrict__ bng, const float* __restrict__ bnb,
                  const float* __restrict__ bnm, const float* __restrict__ bnv)
{
    __shared__ __align__(16) unsigned Ah[16][SMS];
    __shared__ __align__(16) unsigned Al[16][SMS];
    __shared__ __align__(16) unsigned Bh[16][SMS];
    __shared__ __align__(16) unsigned Bl[16][SMS];

    int tid = threadIdx.x;
    int wid = tid >> 5, lane = tid & 31;
    int tg = lane >> 2, tq = lane & 3;
    int warpM = wid >> 2, warpN = wid & 3;      // 2 x 4 warps
    int rowBase = blockIdx.x * 128;
    int colBase = blockIdx.y * 128;
    int mW = warpM * 64, nW = warpN * 32;

    float acc[4][4][4];
#pragma unroll
    for (int mi = 0; mi < 4; mi++)
#pragma unroll
        for (int ni = 0; ni < 4; ni++)
#pragma unroll
            for (int r = 0; r < 4; r++) acc[mi][ni][r] = 0.f;

    for (int k0 = 0; k0 < K; k0 += 16) {
        // Load A tile [128 rows x 16 k] -> Ah/Al[k][m]
#pragma unroll
        for (int i = 0; i < 2; i++) {
            int idx = tid + i * 256;
            int r = idx >> 2;
            int kc = (idx & 3) << 2;
            int gr = rowBase + r;
            float4 v = (gr < M) ? *reinterpret_cast<const float4*>(A + (long)gr * K + k0 + kc)
                                : make_float4(0.f, 0.f, 0.f, 0.f);
            unsigned h, l;
            split_tf32(v.x, h, l); Ah[kc + 0][r] = h; Al[kc + 0][r] = l;
            split_tf32(v.y, h, l); Ah[kc + 1][r] = h; Al[kc + 1][r] = l;
            split_tf32(v.z, h, l); Ah[kc + 2][r] = h; Al[kc + 2][r] = l;
            split_tf32(v.w, h, l); Ah[kc + 3][r] = h; Al[kc + 3][r] = l;
        }
        // Load B tile [16 k x 128 n] -> Bh/Bl[k][n] (vectorized stores)
#pragma unroll
        for (int i = 0; i < 2; i++) {
            int idx = tid + i * 256;
            int kr = idx >> 5;
            int nc = (idx & 31) << 2;
            float4 v = *reinterpret_cast<const float4*>(B + (long)(k0 + kr) * N + colBase + nc);
            uint4 hh, ll;
            split_tf32(v.x, hh.x, ll.x);
            split_tf32(v.y, hh.y, ll.y);
            split_tf32(v.z, hh.z, ll.z);
            split_tf32(v.w, hh.w, ll.w);
            *reinterpret_cast<uint4*>(&Bh[kr][nc]) = hh;
            *reinterpret_cast<uint4*>(&Bl[kr][nc]) = ll;
        }
        __syncthreads();

#pragma unroll
        for (int kk = 0; kk < 16; kk += 8) {
            unsigned bh[4][2], bl[4][2];
#pragma unroll
            for (int ni = 0; ni < 4; ni++) {
                int n = nW + ni * 8 + tg;
                bh[ni][0] = Bh[kk + tq][n];
                bh[ni][1] = Bh[kk + tq + 4][n];
                bl[ni][0] = Bl[kk + tq][n];
                bl[ni][1] = Bl[kk + tq + 4][n];
            }
#pragma unroll
            for (int mi = 0; mi < 4; mi++) {
                int m = mW + mi * 16 + tg;
                unsigned ah[4], al[4];
                ah[0] = Ah[kk + tq][m];     ah[1] = Ah[kk + tq][m + 8];
                ah[2] = Ah[kk + tq + 4][m]; ah[3] = Ah[kk + tq + 4][m + 8];
                al[0] = Al[kk + tq][m];     al[1] = Al[kk + tq][m + 8];
                al[2] = Al[kk + tq + 4][m]; al[3] = Al[kk + tq + 4][m + 8];
#pragma unroll
                for (int ni = 0; ni < 4; ni++) {
                    mma_tf32(acc[mi][ni], ah[0], ah[1], ah[2], ah[3], bh[ni][0], bh[ni][1]);
                    mma_tf32(acc[mi][ni], ah[0], ah[1], ah[2], ah[3], bl[ni][0], bl[ni][1]);
                    mma_tf32(acc[mi][ni], al[0], al[1], al[2], al[3], bh[ni][0], bh[ni][1]);
                }
            }
        }
        __syncthreads();
    }

    // Epilogue: c0,c1 at (row tg, cols tq*2, tq*2+1); c2,c3 at row tg+8.
#pragma unroll
    for (int ni = 0; ni < 4; ni++) {
        int c = colBase + nW + ni * 8 + tq * 2;
        float2 bi = *reinterpret_cast<const float2*>(bias + c);
        float scL = 1.f, shL = 0.f, scH = 1.f, shH = 0.f;
        if (EPI == 1) {
            float2 gg = *reinterpret_cast<const float2*>(bng + c);
            float2 gb = *reinterpret_cast<const float2*>(bnb + c);
            float2 gm = *reinterpret_cast<const float2*>(bnm + c);
            float2 gv = *reinterpret_cast<const float2*>(bnv + c);
            scL = gg.x * rsqrtf(gv.x + EPS_BN); shL = gb.x - gm.x * scL;
            scH = gg.y * rsqrtf(gv.y + EPS_BN); shH = gb.y - gm.y * scH;
        }
#pragma unroll
        for (int mi = 0; mi < 4; mi++) {
            int r0 = rowBase + mW + mi * 16 + tg;
#pragma unroll
            for (int half = 0; half < 2; half++) {
                int row = r0 + half * 8;
                if (row < M) {
                    float vL = acc[mi][ni][half * 2 + 0] + bi.x;
                    float vH = acc[mi][ni][half * 2 + 1] + bi.y;
                    float* p = C + (long)row * N + c;
                    if (EPI == 0) {
                        *reinterpret_cast<float2*>(p) = make_float2(vL, vH);
                    } else if (EPI == 1) {
                        *reinterpret_cast<float2*>(p) = make_float2(
                            fmaxf(fmaf(vL, scL, shL), 0.f),
                            fmaxf(fmaf(vH, scH, shH), 0.f));
                    } else {
                        float2 old = *reinterpret_cast<float2*>(p);
                        *reinterpret_cast<float2*>(p) = make_float2(old.x + vL, old.y + vH);
                    }
                }
            }
        }
    }
}

// ---------------------------------------------------------------------------
// Pool: batch is sorted -> chunked register accumulation, flush on change.
// ---------------------------------------------------------------------------
#define POOL_CHUNK 64
__global__ void pool_kernel(const int* __restrict__ batch,
                            const float* __restrict__ gg,
                            const float* __restrict__ gb,
                            const float* __restrict__ gm,
                            const float* __restrict__ gv)
{
    int c = threadIdx.x;
    int n0 = blockIdx.x * POOL_CHUNK;
    int n1 = min(n0 + POOL_CHUNK, N_NODES);
    float sc = gg[c] * rsqrtf(gv[c] + EPS_BN);
    float sh = gb[c] - gm[c] * sc;

    int curg = batch[n0];
    float acc = 0.f, cnt = 0.f;
    for (int n = n0; n < n1; n++) {
        int bg = batch[n];
        float val = fmaxf(fmaf(g_h[(long)n * H + c], sc, sh), 0.f);
        if (bg != curg) {
            atomicAdd(&g_pool[curg * H + c], acc);
            if (c == 0) atomicAdd(&g_cnt[curg], cnt);
            acc = 0.f; cnt = 0.f; curg = bg;
        }
        acc += val; cnt += 1.f;
    }
    atomicAdd(&g_pool[curg * H + c], acc);
    if (c == 0) atomicAdd(&g_cnt[curg], cnt);
}

__global__ void cls_kernel(const float* __restrict__ clinical,
                           const float* __restrict__ cw,
                           const float* __restrict__ cb,
                           float* __restrict__ out)
{
    int tid = threadIdx.x;
    if (tid >= NGRAPH * NCLS) return;
    int g = tid >> 1;
    int c = tid & 1;
    float inv = 1.f / fmaxf(g_cnt[g], 1.f);
    float acc = cb[c];
    for (int j = 0; j < H; j++)
        acc += g_pool[g * H + j] * inv * cw[j * NCLS + c];
    for (int k = 0; k < KCLIN; k++)
        acc += clinical[g * KCLIN + k] * cw[(H + k) * NCLS + c];
    out[g * NCLS + c] = acc;
}

// ---------------------------------------------------------------------------
extern "C" void kernel_launch(void* const* d_in, const int* in_sizes, int n_in,
                              void* d_out, int out_size)
{
    const float* x        = (const float*)d_in[0];
    const int*   ei       = (const int*)  d_in[1];
    const float* eattr    = (const float*)d_in[2];
    const int*   batch    = (const int*)  d_in[3];
    const float* clinical = (const float*)d_in[4];
    const float* lsw = (const float*)d_in[5],  *lsb = (const float*)d_in[6];
    const float* ldw = (const float*)d_in[7],  *ldb = (const float*)d_in[8];
    const float* ew  = (const float*)d_in[9],  *ebp = (const float*)d_in[10];
    const float* t   = (const float*)d_in[11];
    const float* w1  = (const float*)d_in[12], *b1  = (const float*)d_in[13];
    const float* bg  = (const float*)d_in[14], *bb  = (const float*)d_in[15];
    const float* bm  = (const float*)d_in[16], *bv  = (const float*)d_in[17];
    const float* w2  = (const float*)d_in[18], *b2  = (const float*)d_in[19];
    const float* ng  = (const float*)d_in[20], *nb  = (const float*)d_in[21];
    const float* nm  = (const float*)d_in[22], *nv  = (const float*)d_in[23];
    const float* cw  = (const float*)d_in[24], *cb  = (const float*)d_in[25];
    float* out = (float*)d_out;

    const int* src = ei;
    const int* dstp = ei + N_EDGES;

    float *xs, *xd, *hbuf, *obuf, *mid;
    cudaGetSymbolAddress((void**)&xs,   g_xs);
    cudaGetSymbolAddress((void**)&xd,   g_xd);
    cudaGetSymbolAddress((void**)&hbuf, g_h);
    cudaGetSymbolAddress((void**)&obuf, g_out);
    cudaGetSymbolAddress((void**)&mid,  g_mid);

    // CSR build (layer-invariant)
    zero_kernel<<<256, 256>>>();
    hist_kernel<<<(N_EDGES + 255) / 256, 256>>>(dstp);
    scan_local_kernel<<<SCAN_NB, SCAN_B>>>();
    scan_bsum_kernel<<<1, 128>>>();
    scan_add_kernel<<<(N_NODES + 255) / 256, 256>>>();
    scatter_kernel<<<(N_EDGES + 255) / 256, 256>>>(src, dstp, eattr);

    dim3 grid1((N_NODES + 127) / 128, 1);
    dim3 grid2((N_NODES + 127) / 128, 2);

    tgemm_kernel<0><<<grid1, 256>>>(x, lsw, lsb, xs, N_NODES, H, C_IN,
                                    nullptr, nullptr, nullptr, nullptr);
    tgemm_kernel<0><<<grid1, 256>>>(x, ldw, ldb, xd, N_NODES, H, C_IN,
                                    nullptr, nullptr, nullptr, nullptr);

    for (int l = 0; l < NLAYERS; l++) {
        const float* xsl;
        const float* xdl;
        if (l == 0) {
            xsl = xs; xdl = xd;
        } else {
            relubn_kernel<<<512, 256>>>(hbuf, ng + l * H, nb + l * H,
                                        nm + l * H, nv + l * H, xs);
            xsl = xs; xdl = xs;
        }
        gather_kernel<<<(N_NODES * 32 + 255) / 256, 256>>>(
            xsl, xdl, ew + l * H, ebp + l * H, t, l, obuf);

        tgemm_kernel<1><<<grid2, 256>>>(obuf, w1 + (long)l * H * H2, b1 + l * H2,
                                        mid, N_NODES, H2, H,
                                        bg + l * H2, bb + l * H2,
                                        bm + l * H2, bv + l * H2);
        if (l == 0)
            tgemm_kernel<0><<<grid1, 256>>>(mid, w2 + (long)l * H2 * H, b2 + l * H,
                                            hbuf, N_NODES, H, H2,
                                            nullptr, nullptr, nullptr, nullptr);
        else
            tgemm_kernel<2><<<grid1, 256>>>(mid, w2 + (long)l * H2 * H, b2 + l * H,
                                            hbuf, N_NODES, H, H2,
                                            nullptr, nullptr, nullptr, nullptr);
    }

    pool_kernel<<<(N_NODES + POOL_CHUNK - 1) / POOL_CHUNK, H>>>(batch, ng, nb, nm, nv);
    cls_kernel<<<1, 128>>>(clinical, cw, cb, out);
}

// round 4
// speedup vs baseline: 3.1280x; 1.1653x over previous
#include <cuda_runtime.h>
#include <math.h>

// Problem dims (fixed by dataset)
#define N_NODES 50000
#define N_EDGES 500000
#define C_IN    256
#define H       128
#define H2      256
#define NLAYERS 4
#define NGRAPH  64
#define KCLIN   8
#define NCLS    2
#define EPS_MSG 1e-7f
#define EPS_BN  1e-5f

#define SCAN_B  512
#define SCAN_NB ((N_NODES + SCAN_B - 1) / SCAN_B)   // 98
#define SMS 136   // smem row stride in words (mod 32 == 8 -> conflict-free)

// ---------------------------------------------------------------------------
// Scratch (device globals; no allocation allowed)
// ---------------------------------------------------------------------------
__device__ float    g_xsd [N_NODES * 256];   // layer-0 src|dst projections
__device__ float    g_xs  [N_NODES * H];     // r buffer (layers >= 1)
__device__ float    g_h   [N_NODES * H];
__device__ unsigned g_obufh[N_NODES * 64];   // gather out, packed bf16x2 hi
__device__ unsigned g_obufl[N_NODES * 64];   //                        lo
__device__ unsigned g_midh[N_NODES * 128];   // mlp mid, packed (256ch -> 128)
__device__ unsigned g_midl[N_NODES * 128];
__device__ float    g_pool[NGRAPH * H];
__device__ float    g_cnt [NGRAPH];

// Pre-split weights (packed bf16x2 pairs along K)
__device__ unsigned g_B0h[128 * 256], g_B0l[128 * 256];   // input proj concat
__device__ float    g_bias0[256];
__device__ unsigned g_W1h[NLAYERS * 64 * 256], g_W1l[NLAYERS * 64 * 256];
__device__ unsigned g_W2h[NLAYERS * 128 * 128], g_W2l[NLAYERS * 128 * 128];

// CSR build scratch
__device__ int  g_count[N_NODES];
__device__ int  g_row  [N_NODES + 1];
__device__ int  g_bsum [128];
__device__ int2 g_edges[N_EDGES];       // .x = src id, .y = bits of eattr

// ---------------------------------------------------------------------------
// bf16 split helpers
// ---------------------------------------------------------------------------
__device__ __forceinline__ unsigned packbf(float lo, float hi) {
    unsigned r;  // first src -> upper half, second -> lower half
    asm("cvt.rn.bf16x2.f32 %0, %1, %2;" : "=r"(r) : "f"(hi), "f"(lo));
    return r;
}
__device__ __forceinline__ float2 unpackbf(unsigned p) {
    float2 f;
    f.x = __uint_as_float(p << 16);
    f.y = __uint_as_float(p & 0xffff0000u);
    return f;
}
__device__ __forceinline__ void split2(float a, float b, unsigned& h, unsigned& l) {
    h = packbf(a, b);
    float2 f = unpackbf(h);
    l = packbf(a - f.x, b - f.y);
}
__device__ __forceinline__ void mma_bf16(float c[4],
                                         unsigned a0, unsigned a1, unsigned a2, unsigned a3,
                                         unsigned b0, unsigned b1) {
    asm volatile(
        "mma.sync.aligned.m16n8k16.row.col.f32.bf16.bf16.f32 "
        "{%0,%1,%2,%3}, {%4,%5,%6,%7}, {%8,%9}, {%0,%1,%2,%3};"
        : "+f"(c[0]), "+f"(c[1]), "+f"(c[2]), "+f"(c[3])
        : "r"(a0), "r"(a1), "r"(a2), "r"(a3), "r"(b0), "r"(b1));
}

// ---------------------------------------------------------------------------
__global__ void zero_kernel() {
    int i = blockIdx.x * blockDim.x + threadIdx.x;
    int stride = gridDim.x * blockDim.x;
    for (int k = i; k < N_NODES; k += stride) g_count[k] = 0;
    if (i < NGRAPH * H) g_pool[i] = 0.f;
    if (i < NGRAPH) g_cnt[i] = 0.f;
}

// ---------------------------------------------------------------------------
// Weight pre-split kernels (one-time, tiny)
// ---------------------------------------------------------------------------
__global__ void pack_input(const float* __restrict__ lsw, const float* __restrict__ ldw,
                           const float* __restrict__ lsb, const float* __restrict__ ldb) {
    int idx = blockIdx.x * blockDim.x + threadIdx.x;
    if (idx < 256) g_bias0[idx] = (idx < 128) ? lsb[idx] : ldb[idx - 128];
    if (idx >= 128 * 256) return;
    int k2 = idx >> 8, n = idx & 255;
    float v0, v1;
    if (n < 128) { v0 = lsw[(2 * k2) * 128 + n];       v1 = lsw[(2 * k2 + 1) * 128 + n]; }
    else         { v0 = ldw[(2 * k2) * 128 + n - 128]; v1 = ldw[(2 * k2 + 1) * 128 + n - 128]; }
    unsigned h, l; split2(v0, v1, h, l);
    g_B0h[idx] = h; g_B0l[idx] = l;
}

__global__ void pack_w1(const float* __restrict__ w1) {
    int idx = blockIdx.x * blockDim.x + threadIdx.x;
    if (idx >= NLAYERS * 64 * 256) return;
    int l = idx >> 14, rem = idx & 16383;
    int k2 = rem >> 8, n = rem & 255;
    const float* base = w1 + (long)l * 128 * 256;
    unsigned h, lo; split2(base[(2 * k2) * 256 + n], base[(2 * k2 + 1) * 256 + n], h, lo);
    g_W1h[idx] = h; g_W1l[idx] = lo;
}

__global__ void pack_w2(const float* __restrict__ w2) {
    int idx = blockIdx.x * blockDim.x + threadIdx.x;
    if (idx >= NLAYERS * 128 * 128) return;
    int l = idx >> 14, rem = idx & 16383;
    int k2 = rem >> 7, n = rem & 127;
    const float* base = w2 + (long)l * 256 * 128;
    unsigned h, lo; split2(base[(2 * k2) * 128 + n], base[(2 * k2 + 1) * 128 + n], h, lo);
    g_W2h[idx] = h; g_W2l[idx] = lo;
}

// ---------------------------------------------------------------------------
// CSR build: histogram -> 2-level exclusive scan -> scatter
// ---------------------------------------------------------------------------
__global__ void hist_kernel(const int* __restrict__ dst) {
    int i = blockIdx.x * blockDim.x + threadIdx.x;
    if (i < N_EDGES) atomicAdd(&g_count[dst[i]], 1);
}

__global__ void scan_local_kernel() {
    __shared__ int sh[SCAN_B];
    int tid = threadIdx.x;
    int i = blockIdx.x * SCAN_B + tid;
    int v = (i < N_NODES) ? g_count[i] : 0;
    sh[tid] = v;
    __syncthreads();
    for (int off = 1; off < SCAN_B; off <<= 1) {
        int t = (tid >= off) ? sh[tid - off] : 0;
        __syncthreads();
        sh[tid] += t;
        __syncthreads();
    }
    if (i < N_NODES) g_row[i] = sh[tid] - v;
    if (tid == SCAN_B - 1) g_bsum[blockIdx.x] = sh[tid];
}

__global__ void scan_bsum_kernel() {
    __shared__ int sh[128];
    int tid = threadIdx.x;
    int v = (tid < SCAN_NB) ? g_bsum[tid] : 0;
    sh[tid] = v;
    __syncthreads();
    for (int off = 1; off < 128; off <<= 1) {
        int t = (tid >= off) ? sh[tid - off] : 0;
        __syncthreads();
        sh[tid] += t;
        __syncthreads();
    }
    if (tid < SCAN_NB) g_bsum[tid] = sh[tid] - v;
}

__global__ void scan_add_kernel() {
    int i = blockIdx.x * blockDim.x + threadIdx.x;
    if (i < N_NODES) {
        int r = g_row[i] + g_bsum[i / SCAN_B];
        g_row[i] = r;
        g_count[i] = r;
    }
    if (i == 0) g_row[N_NODES] = N_EDGES;
}

__global__ void scatter_kernel(const int* __restrict__ src,
                               const int* __restrict__ dst,
                               const float* __restrict__ eattr) {
    int e = blockIdx.x * blockDim.x + threadIdx.x;
    if (e >= N_EDGES) return;
    int d = dst[e];
    int pos = atomicAdd(&g_count[d], 1);
    g_edges[pos] = make_int2(src[e], __float_as_int(eattr[e]));
}

// ---------------------------------------------------------------------------
// Gather: one warp per dst node. Softmax aggregation without max-shift.
// Emits the result pre-split into packed bf16x2 hi/lo (consumed by w1 GEMM).
// ---------------------------------------------------------------------------
__global__ __launch_bounds__(256)
void gather_kernel(const float* __restrict__ xs, int ldx,
                   const float* __restrict__ xd,
                   const float* __restrict__ ew,
                   const float* __restrict__ eb,
                   const float* __restrict__ tptr, int l)
{
    int warp = (blockIdx.x * blockDim.x + threadIdx.x) >> 5;
    if (warp >= N_NODES) return;
    int lane = threadIdx.x & 31;
    int c0 = lane * 4;

    float4 w4 = *reinterpret_cast<const float4*>(ew + c0);
    float4 b4 = *reinterpret_cast<const float4*>(eb + c0);
    float tv = tptr[l];

    int e0 = g_row[warp];
    int e1 = g_row[warp + 1];

    float n0 = 0.f, n1 = 0.f, n2 = 0.f, n3 = 0.f;
    float d0 = 0.f, d1 = 0.f, d2 = 0.f, d3 = 0.f;

#pragma unroll 2
    for (int e = e0; e < e1; e++) {
        int2 ed = g_edges[e];
        int   s  = ed.x;
        float al = __int_as_float(ed.y);
        float4 x4 = *reinterpret_cast<const float4*>(xs + (long)s * ldx + c0);

        float m0 = fmaxf(fmaf(al, w4.x, b4.x) + x4.x, 0.f) + EPS_MSG;
        float m1 = fmaxf(fmaf(al, w4.y, b4.y) + x4.y, 0.f) + EPS_MSG;
        float m2 = fmaxf(fmaf(al, w4.z, b4.z) + x4.z, 0.f) + EPS_MSG;
        float m3 = fmaxf(fmaf(al, w4.w, b4.w) + x4.w, 0.f) + EPS_MSG;

        float z0 = __expf(m0 * tv);
        float z1 = __expf(m1 * tv);
        float z2 = __expf(m2 * tv);
        float z3 = __expf(m3 * tv);

        d0 += z0; d1 += z1; d2 += z2; d3 += z3;
        n0 = fmaf(m0, z0, n0); n1 = fmaf(m1, z1, n1);
        n2 = fmaf(m2, z2, n2); n3 = fmaf(m3, z3, n3);
    }

    float4 xv = *reinterpret_cast<const float4*>(xd + (long)warp * ldx + c0);
    float ox = n0 / fmaxf(d0, 1e-16f) + xv.x;
    float oy = n1 / fmaxf(d1, 1e-16f) + xv.y;
    float oz = n2 / fmaxf(d2, 1e-16f) + xv.z;
    float ow = n3 / fmaxf(d3, 1e-16f) + xv.w;

    unsigned h0, l0, h1, l1;
    split2(ox, oy, h0, l0);
    split2(oz, ow, h1, l1);
    int p = warp * 64 + (c0 >> 1);
    *reinterpret_cast<uint2*>(g_obufh + p) = make_uint2(h0, h1);
    *reinterpret_cast<uint2*>(g_obufl + p) = make_uint2(l0, l1);
}

// ---------------------------------------------------------------------------
// Tensor-core GEMM, bf16x3 split (AhBh + AhBl + AlBh), fp32 accumulate.
// C[M,N] = A[M,K] @ B[K,N] + bias.  B is pre-split packed.  A either fp32
// (split on load) or pre-split packed.  128x128 tile, BK=32, 8 warps (2x4).
// MODE 0: C = v                      (fp32)
// MODE 1: split(relu(bn(v))) -> CHi/CLo (packed, N/2 per row)
// MODE 2: C += v
// MODE 3: C += v; R = relu(bn_next(C))
// MODE 4: C  = v; R = relu(bn_next(C))
// ---------------------------------------------------------------------------
template<int MODE, bool ASPLIT>
__global__ __launch_bounds__(256)
void bgemm_kernel(const float* __restrict__ Afp,
                  const unsigned* __restrict__ Ah_g, const unsigned* __restrict__ Al_g,
                  const unsigned* __restrict__ Bh_g, const unsigned* __restrict__ Bl_g,
                  const float* __restrict__ bias,
                  float* __restrict__ C,
                  unsigned* __restrict__ CHi, unsigned* __restrict__ CLo,
                  float* __restrict__ R,
                  int M, int N, int K,
                  const float* __restrict__ bng, const float* __restrict__ bnb,
                  const float* __restrict__ bnm, const float* __restrict__ bnv)
{
    __shared__ __align__(16) unsigned Ahs[16][SMS];
    __shared__ __align__(16) unsigned Als[16][SMS];
    __shared__ __align__(16) unsigned Bhs[16][SMS];
    __shared__ __align__(16) unsigned Bls[16][SMS];

    int tid = threadIdx.x;
    int wid = tid >> 5, lane = tid & 31;
    int tg = lane >> 2, tq = lane & 3;
    int warpM = wid >> 2, warpN = wid & 3;
    int rowBase = blockIdx.x * 128;
    int colBase = blockIdx.y * 128;
    int mW = warpM * 64, nW = warpN * 32;
    int K2 = K >> 1;

    float acc[4][4][4];
#pragma unroll
    for (int mi = 0; mi < 4; mi++)
#pragma unroll
        for (int ni = 0; ni < 4; ni++)
#pragma unroll
            for (int r = 0; r < 4; r++) acc[mi][ni][r] = 0.f;

    for (int k0 = 0; k0 < K; k0 += 32) {
        int k20 = k0 >> 1;
        if (ASPLIT) {
#pragma unroll
            for (int i = 0; i < 4; i++) {
                int idx = tid + i * 256;          // 0..1023
                int r = idx >> 3;
                int kc2 = (idx & 7) * 2;
                int gr = rowBase + r;
                uint2 vh = make_uint2(0u, 0u), vl = make_uint2(0u, 0u);
                if (gr < M) {
                    vh = *reinterpret_cast<const uint2*>(Ah_g + (long)gr * K2 + k20 + kc2);
                    vl = *reinterpret_cast<const uint2*>(Al_g + (long)gr * K2 + k20 + kc2);
                }
                Ahs[kc2][r] = vh.x; Ahs[kc2 + 1][r] = vh.y;
                Als[kc2][r] = vl.x; Als[kc2 + 1][r] = vl.y;
            }
        } else {
#pragma unroll
            for (int i = 0; i < 4; i++) {
                int idx = tid + i * 256;
                int r = idx >> 3;
                int kc = (idx & 7) * 4;
                int gr = rowBase + r;
                float4 v = (gr < M) ? *reinterpret_cast<const float4*>(Afp + (long)gr * K + k0 + kc)
                                    : make_float4(0.f, 0.f, 0.f, 0.f);
                unsigned h0, l0, h1, l1;
                split2(v.x, v.y, h0, l0);
                split2(v.z, v.w, h1, l1);
                int kc2 = kc >> 1;
                Ahs[kc2][r] = h0; Ahs[kc2 + 1][r] = h1;
                Als[kc2][r] = l0; Als[kc2 + 1][r] = l1;
            }
        }
#pragma unroll
        for (int i = 0; i < 2; i++) {
            int idx = tid + i * 256;              // 0..511
            int kr = idx >> 5;
            int nc = (idx & 31) * 4;
            uint4 vh = *reinterpret_cast<const uint4*>(Bh_g + (long)(k20 + kr) * N + colBase + nc);
            uint4 vl = *reinterpret_cast<const uint4*>(Bl_g + (long)(k20 + kr) * N + colBase + nc);
            *reinterpret_cast<uint4*>(&Bhs[kr][nc]) = vh;
            *reinterpret_cast<uint4*>(&Bls[kr][nc]) = vl;
        }
        __syncthreads();

#pragma unroll
        for (int kk = 0; kk < 2; kk++) {
            int k2a = kk * 8 + tq, k2b = k2a + 4;
            unsigned bh0[4], bh1[4], bl0[4], bl1[4];
#pragma unroll
            for (int ni = 0; ni < 4; ni++) {
                int n = nW + ni * 8 + tg;
                bh0[ni] = Bhs[k2a][n]; bh1[ni] = Bhs[k2b][n];
                bl0[ni] = Bls[k2a][n]; bl1[ni] = Bls[k2b][n];
            }
#pragma unroll
            for (int mi = 0; mi < 4; mi++) {
                int m = mW + mi * 16 + tg;
                unsigned ah0 = Ahs[k2a][m], ah1 = Ahs[k2a][m + 8];
                unsigned ah2 = Ahs[k2b][m], ah3 = Ahs[k2b][m + 8];
                unsigned al0 = Als[k2a][m], al1 = Als[k2a][m + 8];
                unsigned al2 = Als[k2b][m], al3 = Als[k2b][m + 8];
#pragma unroll
                for (int ni = 0; ni < 4; ni++) {
                    mma_bf16(acc[mi][ni], ah0, ah1, ah2, ah3, bh0[ni], bh1[ni]);
                    mma_bf16(acc[mi][ni], ah0, ah1, ah2, ah3, bl0[ni], bl1[ni]);
                    mma_bf16(acc[mi][ni], al0, al1, al2, al3, bh0[ni], bh1[ni]);
                }
            }
        }
        __syncthreads();
    }

    // Epilogue
#pragma unroll
    for (int ni = 0; ni < 4; ni++) {
        int c = colBase + nW + ni * 8 + tq * 2;
        float2 bi = *reinterpret_cast<const float2*>(bias + c);
        float scL = 1.f, shL = 0.f, scH = 1.f, shH = 0.f;
        if (MODE == 1 || MODE == 3 || MODE == 4) {
            float2 gg = *reinterpret_cast<const float2*>(bng + c);
            float2 gb = *reinterpret_cast<const float2*>(bnb + c);
            float2 gm = *reinterpret_cast<const float2*>(bnm + c);
            float2 gv = *reinterpret_cast<const float2*>(bnv + c);
            scL = gg.x * rsqrtf(gv.x + EPS_BN); shL = gb.x - gm.x * scL;
            scH = gg.y * rsqrtf(gv.y + EPS_BN); shH = gb.y - gm.y * scH;
        }
#pragma unroll
        for (int mi = 0; mi < 4; mi++) {
            int r0 = rowBase + mW + mi * 16 + tg;
#pragma unroll
            for (int half = 0; half < 2; half++) {
                int row = r0 + half * 8;
                if (row >= M) continue;
                float vL = acc[mi][ni][half * 2 + 0] + bi.x;
                float vH = acc[mi][ni][half * 2 + 1] + bi.y;
                if (MODE == 0) {
                    *reinterpret_cast<float2*>(C + (long)row * N + c) = make_float2(vL, vH);
                } else if (MODE == 1) {
                    float tL = fmaxf(fmaf(vL, scL, shL), 0.f);
                    float tH = fmaxf(fmaf(vH, scH, shH), 0.f);
                    unsigned hp, lp; split2(tL, tH, hp, lp);
                    long pidx = (long)row * (N >> 1) + (c >> 1);
                    CHi[pidx] = hp; CLo[pidx] = lp;
                } else if (MODE == 2) {
                    float2* p = reinterpret_cast<float2*>(C + (long)row * N + c);
                    float2 old = *p;
                    *p = make_float2(old.x + vL, old.y + vH);
                } else if (MODE == 3) {
                    float2* p = reinterpret_cast<float2*>(C + (long)row * N + c);
                    float2 old = *p;
                    float hL = old.x + vL, hH = old.y + vH;
                    *p = make_float2(hL, hH);
                    *reinterpret_cast<float2*>(R + (long)row * N + c) = make_float2(
                        fmaxf(fmaf(hL, scL, shL), 0.f), fmaxf(fmaf(hH, scH, shH), 0.f));
                } else { // MODE 4
                    *reinterpret_cast<float2*>(C + (long)row * N + c) = make_float2(vL, vH);
                    *reinterpret_cast<float2*>(R + (long)row * N + c) = make_float2(
                        fmaxf(fmaf(vL, scL, shL), 0.f), fmaxf(fmaf(vH, scH, shH), 0.f));
                }
            }
        }
    }
}

// ---------------------------------------------------------------------------
// Pool: batch is sorted -> chunked register accumulation, flush on change.
// ---------------------------------------------------------------------------
#define POOL_CHUNK 64
__global__ void pool_kernel(const int* __restrict__ batch,
                            const float* __restrict__ gg,
                            const float* __restrict__ gb,
                            const float* __restrict__ gm,
                            const float* __restrict__ gv)
{
    int c = threadIdx.x;
    int n0 = blockIdx.x * POOL_CHUNK;
    int n1 = min(n0 + POOL_CHUNK, N_NODES);
    float sc = gg[c] * rsqrtf(gv[c] + EPS_BN);
    float sh = gb[c] - gm[c] * sc;

    int curg = batch[n0];
    float acc = 0.f, cnt = 0.f;
    for (int n = n0; n < n1; n++) {
        int bg = batch[n];
        float val = fmaxf(fmaf(g_h[(long)n * H + c], sc, sh), 0.f);
        if (bg != curg) {
            atomicAdd(&g_pool[curg * H + c], acc);
            if (c == 0) atomicAdd(&g_cnt[curg], cnt);
            acc = 0.f; cnt = 0.f; curg = bg;
        }
        acc += val; cnt += 1.f;
    }
    atomicAdd(&g_pool[curg * H + c], acc);
    if (c == 0) atomicAdd(&g_cnt[curg], cnt);
}

__global__ void cls_kernel(const float* __restrict__ clinical,
                           const float* __restrict__ cw,
                           const float* __restrict__ cb,
                           float* __restrict__ out)
{
    int tid = threadIdx.x;
    if (tid >= NGRAPH * NCLS) return;
    int g = tid >> 1;
    int c = tid & 1;
    float inv = 1.f / fmaxf(g_cnt[g], 1.f);
    float acc = cb[c];
    for (int j = 0; j < H; j++)
        acc += g_pool[g * H + j] * inv * cw[j * NCLS + c];
    for (int k = 0; k < KCLIN; k++)
        acc += clinical[g * KCLIN + k] * cw[(H + k) * NCLS + c];
    out[g * NCLS + c] = acc;
}

// ---------------------------------------------------------------------------
extern "C" void kernel_launch(void* const* d_in, const int* in_sizes, int n_in,
                              void* d_out, int out_size)
{
    const float* x        = (const float*)d_in[0];
    const int*   ei       = (const int*)  d_in[1];
    const float* eattr    = (const float*)d_in[2];
    const int*   batch    = (const int*)  d_in[3];
    const float* clinical = (const float*)d_in[4];
    const float* lsw = (const float*)d_in[5],  *lsb = (const float*)d_in[6];
    const float* ldw = (const float*)d_in[7],  *ldb = (const float*)d_in[8];
    const float* ew  = (const float*)d_in[9],  *ebp = (const float*)d_in[10];
    const float* t   = (const float*)d_in[11];
    const float* w1  = (const float*)d_in[12], *b1  = (const float*)d_in[13];
    const float* bg  = (const float*)d_in[14], *bb  = (const float*)d_in[15];
    const float* bm  = (const float*)d_in[16], *bv  = (const float*)d_in[17];
    const float* w2  = (const float*)d_in[18], *b2  = (const float*)d_in[19];
    const float* ng  = (const float*)d_in[20], *nb  = (const float*)d_in[21];
    const float* nm  = (const float*)d_in[22], *nv  = (const float*)d_in[23];
    const float* cw  = (const float*)d_in[24], *cb  = (const float*)d_in[25];
    float* out = (float*)d_out;

    const int* src = ei;
    const int* dstp = ei + N_EDGES;

    float *xsd, *xsr, *hbuf;
    unsigned *obh, *obl, *mdh, *mdl, *B0h, *B0l, *W1h, *W1l, *W2h, *W2l;
    float *bias0;
    cudaGetSymbolAddress((void**)&xsd,  g_xsd);
    cudaGetSymbolAddress((void**)&xsr,  g_xs);
    cudaGetSymbolAddress((void**)&hbuf, g_h);
    cudaGetSymbolAddress((void**)&obh,  g_obufh);
    cudaGetSymbolAddress((void**)&obl,  g_obufl);
    cudaGetSymbolAddress((void**)&mdh,  g_midh);
    cudaGetSymbolAddress((void**)&mdl,  g_midl);
    cudaGetSymbolAddress((void**)&B0h,  g_B0h);
    cudaGetSymbolAddress((void**)&B0l,  g_B0l);
    cudaGetSymbolAddress((void**)&W1h,  g_W1h);
    cudaGetSymbolAddress((void**)&W1l,  g_W1l);
    cudaGetSymbolAddress((void**)&W2h,  g_W2h);
    cudaGetSymbolAddress((void**)&W2l,  g_W2l);
    cudaGetSymbolAddress((void**)&bias0, g_bias0);

    // CSR build (layer-invariant) + weight pre-split
    zero_kernel<<<256, 256>>>();
    hist_kernel<<<(N_EDGES + 255) / 256, 256>>>(dstp);
    scan_local_kernel<<<SCAN_NB, SCAN_B>>>();
    scan_bsum_kernel<<<1, 128>>>();
    scan_add_kernel<<<(N_NODES + 255) / 256, 256>>>();
    scatter_kernel<<<(N_EDGES + 255) / 256, 256>>>(src, dstp, eattr);
    pack_input<<<128, 256>>>(lsw, ldw, lsb, ldb);
    pack_w1<<<256, 256>>>(w1);
    pack_w2<<<256, 256>>>(w2);

    dim3 grid1((N_NODES + 127) / 128, 1);
    dim3 grid2((N_NODES + 127) / 128, 2);

    // Input projection: xsd = x @ [lin_src_w | lin_dst_w] + bias_cat
    bgemm_kernel<0, false><<<grid2, 256>>>(x, nullptr, nullptr, B0h, B0l, bias0,
                                           xsd, nullptr, nullptr, nullptr,
                                           N_NODES, 256, 256,
                                           nullptr, nullptr, nullptr, nullptr);

    for (int l = 0; l < NLAYERS; l++) {
        if (l == 0)
            gather_kernel<<<(N_NODES * 32 + 255) / 256, 256>>>(
                xsd, 256, xsd + 128, ew + l * H, ebp + l * H, t, l);
        else
            gather_kernel<<<(N_NODES * 32 + 255) / 256, 256>>>(
                xsr, 128, xsr, ew + l * H, ebp + l * H, t, l);

        // mid = split(relu(bn(obuf @ w1 + b1)))
        bgemm_kernel<1, true><<<grid2, 256>>>(nullptr, obh, obl,
                                              W1h + l * 16384, W1l + l * 16384,
                                              b1 + l * H2,
                                              nullptr, mdh, mdl, nullptr,
                                              N_NODES, H2, H,
                                              bg + l * H2, bb + l * H2,
                                              bm + l * H2, bv + l * H2);

        // h (+)= mid @ w2 + b2 ; r = relu(bn_{l+1}(h)) fused when needed
        if (l == 0)
            bgemm_kernel<4, true><<<grid1, 256>>>(nullptr, mdh, mdl,
                                                  W2h + l * 16384, W2l + l * 16384,
                                                  b2 + l * H,
                                                  hbuf, nullptr, nullptr, xsr,
                                                  N_NODES, H, H2,
                                                  ng + (l + 1) * H, nb + (l + 1) * H,
                                                  nm + (l + 1) * H, nv + (l + 1) * H);
        else if (l < NLAYERS - 1)
            bgemm_kernel<3, true><<<grid1, 256>>>(nullptr, mdh, mdl,
                                                  W2h + l * 16384, W2l + l * 16384,
                                                  b2 + l * H,
                                                  hbuf, nullptr, nullptr, xsr,
                                                  N_NODES, H, H2,
                                                  ng + (l + 1) * H, nb + (l + 1) * H,
                                                  nm + (l + 1) * H, nv + (l + 1) * H);
        else
            bgemm_kernel<2, true><<<grid1, 256>>>(nullptr, mdh, mdl,
                                                  W2h + l * 16384, W2l + l * 16384,
                                                  b2 + l * H,
                                                  hbuf, nullptr, nullptr, nullptr,
                                                  N_NODES, H, H2,
                                                  nullptr, nullptr, nullptr, nullptr);
    }

    pool_kernel<<<(N_NODES + POOL_CHUNK - 1) / POOL_CHUNK, H>>>(batch, ng, nb, nm, nv);
    cls_kernel<<<1, 128>>>(clinical, cw, cb, out);
}

// round 5
// speedup vs baseline: 3.5182x; 1.1247x over previous
#include <cuda_runtime.h>
#include <math.h>

// Problem dims (fixed by dataset)
#define N_NODES 50000
#define N_EDGES 500000
#define C_IN    256
#define H       128
#define H2      256
#define NLAYERS 4
#define NGRAPH  64
#define KCLIN   8
#define NCLS    2
#define EPS_MSG 1e-7f
#define EPS_BN  1e-5f

#define SCAN_B  512
#define SCAN_NB ((N_NODES + SCAN_B - 1) / SCAN_B)   // 98
#define SMS 136   // B smem row stride in words (mod 32 == 8 -> conflict-free)
#define ASTRIDE 20 // A smem row stride (mod 32 == 20 -> conflict-free frags)

// ---------------------------------------------------------------------------
// Scratch (device globals; no allocation allowed)
// ---------------------------------------------------------------------------
__device__ float    g_xsd [N_NODES * 256];   // layer-0 src|dst projections
__device__ float    g_xs  [N_NODES * H];     // r buffer (layers >= 1)
__device__ float    g_h   [N_NODES * H];
__device__ unsigned g_obufh[N_NODES * 64];   // gather out, packed bf16x2 hi
__device__ unsigned g_obufl[N_NODES * 64];
__device__ unsigned g_midh[N_NODES * 128];   // mlp mid, packed
__device__ unsigned g_midl[N_NODES * 128];
__device__ float    g_pool[NGRAPH * H];
__device__ float    g_cnt [NGRAPH];

// Pre-split weights (packed bf16x2 pairs along K)
__device__ unsigned g_B0h[128 * 256], g_B0l[128 * 256];
__device__ float    g_bias0[256];
__device__ unsigned g_W1h[NLAYERS * 64 * 256], g_W1l[NLAYERS * 64 * 256];
__device__ unsigned g_W2h[NLAYERS * 128 * 128], g_W2l[NLAYERS * 128 * 128];

// CSR build scratch
__device__ int  g_count[N_NODES];
__device__ int  g_row  [N_NODES + 1];
__device__ int  g_bsum [128];
__device__ int2 g_edges[N_EDGES];

// ---------------------------------------------------------------------------
// helpers
// ---------------------------------------------------------------------------
__device__ __forceinline__ unsigned packbf(float lo, float hi) {
    unsigned r;
    asm("cvt.rn.bf16x2.f32 %0, %1, %2;" : "=r"(r) : "f"(hi), "f"(lo));
    return r;
}
__device__ __forceinline__ float2 unpackbf(unsigned p) {
    float2 f;
    f.x = __uint_as_float(p << 16);
    f.y = __uint_as_float(p & 0xffff0000u);
    return f;
}
__device__ __forceinline__ void split2(float a, float b, unsigned& h, unsigned& l) {
    h = packbf(a, b);
    float2 f = unpackbf(h);
    l = packbf(a - f.x, b - f.y);
}
__device__ __forceinline__ void mma_bf16(float c[4],
                                         unsigned a0, unsigned a1, unsigned a2, unsigned a3,
                                         unsigned b0, unsigned b1) {
    asm volatile(
        "mma.sync.aligned.m16n8k16.row.col.f32.bf16.bf16.f32 "
        "{%0,%1,%2,%3}, {%4,%5,%6,%7}, {%8,%9}, {%0,%1,%2,%3};"
        : "+f"(c[0]), "+f"(c[1]), "+f"(c[2]), "+f"(c[3])
        : "r"(a0), "r"(a1), "r"(a2), "r"(a3), "r"(b0), "r"(b1));
}
__device__ __forceinline__ void cp_async8(void* smem, const void* gmem, bool pred) {
    unsigned sa = (unsigned)__cvta_generic_to_shared(smem);
    int sz = pred ? 8 : 0;
    asm volatile("cp.async.ca.shared.global [%0], [%1], 8, %2;\n"
                 :: "r"(sa), "l"(gmem), "r"(sz));
}
__device__ __forceinline__ void cp_async16(void* smem, const void* gmem) {
    unsigned sa = (unsigned)__cvta_generic_to_shared(smem);
    asm volatile("cp.async.cg.shared.global [%0], [%1], 16;\n"
                 :: "r"(sa), "l"(gmem));
}
__device__ __forceinline__ void cp_commit() {
    asm volatile("cp.async.commit_group;\n" ::);
}
template<int W> __device__ __forceinline__ void cp_wait() {
    asm volatile("cp.async.wait_group %0;\n" :: "n"(W));
}

// ---------------------------------------------------------------------------
// pack_all: zero accumulators + pre-split all weights (one launch)
// ---------------------------------------------------------------------------
__global__ void pack_all(const float* __restrict__ lsw, const float* __restrict__ ldw,
                         const float* __restrict__ lsb, const float* __restrict__ ldb,
                         const float* __restrict__ w1, const float* __restrict__ w2)
{
    int i = blockIdx.x * blockDim.x + threadIdx.x;
    int stride = gridDim.x * blockDim.x;
    for (int k = i; k < N_NODES; k += stride) g_count[k] = 0;
    if (i < NGRAPH * H) g_pool[i] = 0.f;
    if (i < NGRAPH) g_cnt[i] = 0.f;
    if (i < 256) g_bias0[i] = (i < 128) ? lsb[i] : ldb[i - 128];

    for (int idx = i; idx < 128 * 256; idx += stride) {
        int k2 = idx >> 8, n = idx & 255;
        float v0, v1;
        if (n < 128) { v0 = lsw[(2*k2)*128 + n];       v1 = lsw[(2*k2+1)*128 + n]; }
        else         { v0 = ldw[(2*k2)*128 + n - 128]; v1 = ldw[(2*k2+1)*128 + n - 128]; }
        unsigned h, l; split2(v0, v1, h, l);
        g_B0h[idx] = h; g_B0l[idx] = l;
    }
    for (int idx = i; idx < NLAYERS * 64 * 256; idx += stride) {
        int l = idx >> 14, rem = idx & 16383;
        int k2 = rem >> 8, n = rem & 255;
        const float* base = w1 + (long)l * 128 * 256;
        unsigned h, lo; split2(base[(2*k2)*256 + n], base[(2*k2+1)*256 + n], h, lo);
        g_W1h[idx] = h; g_W1l[idx] = lo;
    }
    for (int idx = i; idx < NLAYERS * 128 * 128; idx += stride) {
        int l = idx >> 14, rem = idx & 16383;
        int k2 = rem >> 7, n = rem & 127;
        const float* base = w2 + (long)l * 256 * 128;
        unsigned h, lo; split2(base[(2*k2)*128 + n], base[(2*k2+1)*128 + n], h, lo);
        g_W2h[idx] = h; g_W2l[idx] = lo;
    }
}

// ---------------------------------------------------------------------------
// CSR build
// ---------------------------------------------------------------------------
__global__ void hist_kernel(const int* __restrict__ dst) {
    int i = blockIdx.x * blockDim.x + threadIdx.x;
    if (i < N_EDGES) atomicAdd(&g_count[dst[i]], 1);
}

__global__ void scan_local_kernel() {
    __shared__ int sh[SCAN_B];
    int tid = threadIdx.x;
    int i = blockIdx.x * SCAN_B + tid;
    int v = (i < N_NODES) ? g_count[i] : 0;
    sh[tid] = v;
    __syncthreads();
    for (int off = 1; off < SCAN_B; off <<= 1) {
        int t = (tid >= off) ? sh[tid - off] : 0;
        __syncthreads();
        sh[tid] += t;
        __syncthreads();
    }
    if (i < N_NODES) g_row[i] = sh[tid] - v;
    if (tid == SCAN_B - 1) g_bsum[blockIdx.x] = sh[tid];
}

__global__ void scan_bsum_kernel() {
    __shared__ int sh[128];
    int tid = threadIdx.x;
    int v = (tid < SCAN_NB) ? g_bsum[tid] : 0;
    sh[tid] = v;
    __syncthreads();
    for (int off = 1; off < 128; off <<= 1) {
        int t = (tid >= off) ? sh[tid - off] : 0;
        __syncthreads();
        sh[tid] += t;
        __syncthreads();
    }
    if (tid < SCAN_NB) g_bsum[tid] = sh[tid] - v;
}

__global__ void scan_add_kernel() {
    int i = blockIdx.x * blockDim.x + threadIdx.x;
    if (i < N_NODES) {
        int r = g_row[i] + g_bsum[i / SCAN_B];
        g_row[i] = r;
        g_count[i] = r;
    }
    if (i == 0) g_row[N_NODES] = N_EDGES;
}

__global__ void scatter_kernel(const int* __restrict__ src,
                               const int* __restrict__ dst,
                               const float* __restrict__ eattr) {
    int e = blockIdx.x * blockDim.x + threadIdx.x;
    if (e >= N_EDGES) return;
    int d = dst[e];
    int pos = atomicAdd(&g_count[d], 1);
    g_edges[pos] = make_int2(src[e], __float_as_int(eattr[e]));
}

// ---------------------------------------------------------------------------
// Gather: one warp per dst node; softmax aggregation without max-shift.
// Emits packed bf16x2 hi/lo for the following w1 GEMM.
// ---------------------------------------------------------------------------
__global__ __launch_bounds__(256)
void gather_kernel(const float* __restrict__ xs, int ldx,
                   const float* __restrict__ xd,
                   const float* __restrict__ ew,
                   const float* __restrict__ eb,
                   const float* __restrict__ tptr, int l)
{
    int warp = (blockIdx.x * blockDim.x + threadIdx.x) >> 5;
    if (warp >= N_NODES) return;
    int lane = threadIdx.x & 31;
    int c0 = lane * 4;

    float4 w4 = *reinterpret_cast<const float4*>(ew + c0);
    float4 b4 = *reinterpret_cast<const float4*>(eb + c0);
    float tv = tptr[l];

    int e0 = g_row[warp];
    int e1 = g_row[warp + 1];

    float n0 = 0.f, n1 = 0.f, n2 = 0.f, n3 = 0.f;
    float d0 = 0.f, d1 = 0.f, d2 = 0.f, d3 = 0.f;

#pragma unroll 4
    for (int e = e0; e < e1; e++) {
        int2 ed = g_edges[e];
        int   s  = ed.x;
        float al = __int_as_float(ed.y);
        float4 x4 = *reinterpret_cast<const float4*>(xs + (long)s * ldx + c0);

        float m0 = fmaxf(fmaf(al, w4.x, b4.x) + x4.x, 0.f) + EPS_MSG;
        float m1 = fmaxf(fmaf(al, w4.y, b4.y) + x4.y, 0.f) + EPS_MSG;
        float m2 = fmaxf(fmaf(al, w4.z, b4.z) + x4.z, 0.f) + EPS_MSG;
        float m3 = fmaxf(fmaf(al, w4.w, b4.w) + x4.w, 0.f) + EPS_MSG;

        float z0 = __expf(m0 * tv);
        float z1 = __expf(m1 * tv);
        float z2 = __expf(m2 * tv);
        float z3 = __expf(m3 * tv);

        d0 += z0; d1 += z1; d2 += z2; d3 += z3;
        n0 = fmaf(m0, z0, n0); n1 = fmaf(m1, z1, n1);
        n2 = fmaf(m2, z2, n2); n3 = fmaf(m3, z3, n3);
    }

    float4 xv = *reinterpret_cast<const float4*>(xd + (long)warp * ldx + c0);
    float ox = n0 / fmaxf(d0, 1e-16f) + xv.x;
    float oy = n1 / fmaxf(d1, 1e-16f) + xv.y;
    float oz = n2 / fmaxf(d2, 1e-16f) + xv.z;
    float ow = n3 / fmaxf(d3, 1e-16f) + xv.w;

    unsigned h0, l0, h1, l1;
    split2(ox, oy, h0, l0);
    split2(oz, ow, h1, l1);
    int p = warp * 64 + (c0 >> 1);
    *reinterpret_cast<uint2*>(g_obufh + p) = make_uint2(h0, h1);
    *reinterpret_cast<uint2*>(g_obufl + p) = make_uint2(l0, l1);
}

// ---------------------------------------------------------------------------
// fp32-input GEMM (input projection only). Single-buffered, static smem.
// C = A[M,K] @ B[K,N] + bias (bf16x3 split on load).
// ---------------------------------------------------------------------------
__global__ __launch_bounds__(256)
void bgemm_fp32(const float* __restrict__ Afp,
                const unsigned* __restrict__ Bh_g, const unsigned* __restrict__ Bl_g,
                const float* __restrict__ bias, float* __restrict__ C,
                int M, int N, int K)
{
    __shared__ __align__(16) unsigned Ahs[16][SMS];
    __shared__ __align__(16) unsigned Als[16][SMS];
    __shared__ __align__(16) unsigned Bhs[16][SMS];
    __shared__ __align__(16) unsigned Bls[16][SMS];

    int tid = threadIdx.x;
    int wid = tid >> 5, lane = tid & 31;
    int tg = lane >> 2, tq = lane & 3;
    int warpM = wid >> 2, warpN = wid & 3;
    int rowBase = blockIdx.x * 128;
    int colBase = blockIdx.y * 128;
    int mW = warpM * 64, nW = warpN * 32;

    float acc[4][4][4];
#pragma unroll
    for (int mi = 0; mi < 4; mi++)
#pragma unroll
        for (int ni = 0; ni < 4; ni++)
#pragma unroll
            for (int r = 0; r < 4; r++) acc[mi][ni][r] = 0.f;

    for (int k0 = 0; k0 < K; k0 += 32) {
        int k20 = k0 >> 1;
#pragma unroll
        for (int i = 0; i < 4; i++) {
            int idx = tid + i * 256;
            int r = idx >> 3;
            int kc = (idx & 7) * 4;
            int gr = rowBase + r;
            float4 v = (gr < M) ? *reinterpret_cast<const float4*>(Afp + (long)gr * K + k0 + kc)
                                : make_float4(0.f, 0.f, 0.f, 0.f);
            unsigned h0, l0, h1, l1;
            split2(v.x, v.y, h0, l0);
            split2(v.z, v.w, h1, l1);
            int kc2 = kc >> 1;
            Ahs[kc2][r] = h0; Ahs[kc2 + 1][r] = h1;
            Als[kc2][r] = l0; Als[kc2 + 1][r] = l1;
        }
#pragma unroll
        for (int i = 0; i < 2; i++) {
            int idx = tid + i * 256;
            int kr = idx >> 5;
            int nc = (idx & 31) * 4;
            uint4 vh = *reinterpret_cast<const uint4*>(Bh_g + (long)(k20 + kr) * N + colBase + nc);
            uint4 vl = *reinterpret_cast<const uint4*>(Bl_g + (long)(k20 + kr) * N + colBase + nc);
            *reinterpret_cast<uint4*>(&Bhs[kr][nc]) = vh;
            *reinterpret_cast<uint4*>(&Bls[kr][nc]) = vl;
        }
        __syncthreads();

#pragma unroll
        for (int kk = 0; kk < 2; kk++) {
            int k2a = kk * 8 + tq, k2b = k2a + 4;
            unsigned bh0[4], bh1[4], bl0[4], bl1[4];
#pragma unroll
            for (int ni = 0; ni < 4; ni++) {
                int n = nW + ni * 8 + tg;
                bh0[ni] = Bhs[k2a][n]; bh1[ni] = Bhs[k2b][n];
                bl0[ni] = Bls[k2a][n]; bl1[ni] = Bls[k2b][n];
            }
#pragma unroll
            for (int mi = 0; mi < 4; mi++) {
                int m = mW + mi * 16 + tg;
                unsigned ah0 = Ahs[k2a][m], ah1 = Ahs[k2a][m + 8];
                unsigned ah2 = Ahs[k2b][m], ah3 = Ahs[k2b][m + 8];
                unsigned al0 = Als[k2a][m], al1 = Als[k2a][m + 8];
                unsigned al2 = Als[k2b][m], al3 = Als[k2b][m + 8];
#pragma unroll
                for (int ni = 0; ni < 4; ni++) {
                    mma_bf16(acc[mi][ni], ah0, ah1, ah2, ah3, bh0[ni], bh1[ni]);
                    mma_bf16(acc[mi][ni], ah0, ah1, ah2, ah3, bl0[ni], bl1[ni]);
                    mma_bf16(acc[mi][ni], al0, al1, al2, al3, bh0[ni], bh1[ni]);
                }
            }
        }
        __syncthreads();
    }

#pragma unroll
    for (int ni = 0; ni < 4; ni++) {
        int c = colBase + nW + ni * 8 + tq * 2;
        float2 bi = *reinterpret_cast<const float2*>(bias + c);
#pragma unroll
        for (int mi = 0; mi < 4; mi++) {
            int r0 = rowBase + mW + mi * 16 + tg;
#pragma unroll
            for (int half = 0; half < 2; half++) {
                int row = r0 + half * 8;
                if (row >= M) continue;
                float vL = acc[mi][ni][half * 2 + 0] + bi.x;
                float vH = acc[mi][ni][half * 2 + 1] + bi.y;
                *reinterpret_cast<float2*>(C + (long)row * N + c) = make_float2(vL, vH);
            }
        }
    }
}

// ---------------------------------------------------------------------------
// Pipelined GEMM (pre-split packed A) with cp.async double buffering.
// MODE 1: split(relu(bn(v))) -> CHi/CLo (packed)
// MODE 2: C += v
// MODE 3: C += v; R = relu(bn_next(C))
// MODE 4: C  = v; R = relu(bn_next(C))
// Dynamic smem: Ah[2][128][20], Al[2][128][20], Bh[2][16][136], Bl[2][16][136]
// ---------------------------------------------------------------------------
#define PIPE_SMEM ((2*128*ASTRIDE*2 + 2*16*SMS*2) * 4)

template<int MODE>
__global__ __launch_bounds__(256)
void bgemm_pipe(const unsigned* __restrict__ Ah_g, const unsigned* __restrict__ Al_g,
                const unsigned* __restrict__ Bh_g, const unsigned* __restrict__ Bl_g,
                const float* __restrict__ bias,
                float* __restrict__ C,
                unsigned* __restrict__ CHi, unsigned* __restrict__ CLo,
                float* __restrict__ R,
                int M, int N, int K,
                const float* __restrict__ bng, const float* __restrict__ bnb,
                const float* __restrict__ bnm, const float* __restrict__ bnv)
{
    extern __shared__ unsigned smem_[];
    unsigned* Ah = smem_;                         // [2][128][ASTRIDE]
    unsigned* Al = Ah + 2 * 128 * ASTRIDE;
    unsigned* Bh = Al + 2 * 128 * ASTRIDE;        // [2][16][SMS]
    unsigned* Bl = Bh + 2 * 16 * SMS;
#define AHS(s,r,k) Ah[((s)*128 + (r)) * ASTRIDE + (k)]
#define ALS(s,r,k) Al[((s)*128 + (r)) * ASTRIDE + (k)]
#define BHS(s,r,n) Bh[((s)*16 + (r)) * SMS + (n)]
#define BLS(s,r,n) Bl[((s)*16 + (r)) * SMS + (n)]

    int tid = threadIdx.x;
    int wid = tid >> 5, lane = tid & 31;
    int tg = lane >> 2, tq = lane & 3;
    int warpM = wid >> 2, warpN = wid & 3;
    int rowBase = blockIdx.x * 128;
    int colBase = blockIdx.y * 128;
    int mW = warpM * 64, nW = warpN * 32;
    int K2 = K >> 1;

    float acc[4][4][4];
#pragma unroll
    for (int mi = 0; mi < 4; mi++)
#pragma unroll
        for (int ni = 0; ni < 4; ni++)
#pragma unroll
            for (int r = 0; r < 4; r++) acc[mi][ni][r] = 0.f;

    auto load_stage = [&](int s, int k0) {
        int k20 = k0 >> 1;
#pragma unroll
        for (int i = 0; i < 4; i++) {
            int idx = tid + i * 256;
            int r = idx >> 3;
            int kc2 = (idx & 7) * 2;
            int gr = rowBase + r;
            bool ok = gr < M;
            long off = (long)(ok ? gr : 0) * K2 + k20 + kc2;
            cp_async8(&AHS(s, r, kc2), Ah_g + off, ok);
            cp_async8(&ALS(s, r, kc2), Al_g + off, ok);
        }
#pragma unroll
        for (int i = 0; i < 2; i++) {
            int idx = tid + i * 256;
            int kr = idx >> 5;
            int nc = (idx & 31) * 4;
            long off = (long)(k20 + kr) * N + colBase + nc;
            cp_async16(&BHS(s, kr, nc), Bh_g + off);
            cp_async16(&BLS(s, kr, nc), Bl_g + off);
        }
        cp_commit();
    };

    int nIter = K >> 5;
    load_stage(0, 0);

    for (int it = 0; it < nIter; it++) {
        if (it + 1 < nIter) {
            load_stage((it + 1) & 1, (it + 1) << 5);
            cp_wait<1>();
        } else {
            cp_wait<0>();
        }
        __syncthreads();

        int s = it & 1;
#pragma unroll
        for (int kk = 0; kk < 2; kk++) {
            int k2a = kk * 8 + tq, k2b = k2a + 4;
            unsigned bh0[4], bh1[4], bl0[4], bl1[4];
#pragma unroll
            for (int ni = 0; ni < 4; ni++) {
                int n = nW + ni * 8 + tg;
                bh0[ni] = BHS(s, k2a, n); bh1[ni] = BHS(s, k2b, n);
                bl0[ni] = BLS(s, k2a, n); bl1[ni] = BLS(s, k2b, n);
            }
#pragma unroll
            for (int mi = 0; mi < 4; mi++) {
                int m = mW + mi * 16 + tg;
                unsigned ah0 = AHS(s, m, k2a), ah1 = AHS(s, m + 8, k2a);
                unsigned ah2 = AHS(s, m, k2b), ah3 = AHS(s, m + 8, k2b);
                unsigned al0 = ALS(s, m, k2a), al1 = ALS(s, m + 8, k2a);
                unsigned al2 = ALS(s, m, k2b), al3 = ALS(s, m + 8, k2b);
#pragma unroll
                for (int ni = 0; ni < 4; ni++) {
                    mma_bf16(acc[mi][ni], ah0, ah1, ah2, ah3, bh0[ni], bh1[ni]);
                    mma_bf16(acc[mi][ni], ah0, ah1, ah2, ah3, bl0[ni], bl1[ni]);
                    mma_bf16(acc[mi][ni], al0, al1, al2, al3, bh0[ni], bh1[ni]);
                }
            }
        }
        __syncthreads();
    }

    // Epilogue
#pragma unroll
    for (int ni = 0; ni < 4; ni++) {
        int c = colBase + nW + ni * 8 + tq * 2;
        float2 bi = *reinterpret_cast<const float2*>(bias + c);
        float scL = 1.f, shL = 0.f, scH = 1.f, shH = 0.f;
        if (MODE == 1 || MODE == 3 || MODE == 4) {
            float2 gg = *reinterpret_cast<const float2*>(bng + c);
            float2 gb = *reinterpret_cast<const float2*>(bnb + c);
            float2 gm = *reinterpret_cast<const float2*>(bnm + c);
            float2 gv = *reinterpret_cast<const float2*>(bnv + c);
            scL = gg.x * rsqrtf(gv.x + EPS_BN); shL = gb.x - gm.x * scL;
            scH = gg.y * rsqrtf(gv.y + EPS_BN); shH = gb.y - gm.y * scH;
        }
#pragma unroll
        for (int mi = 0; mi < 4; mi++) {
            int r0 = rowBase + mW + mi * 16 + tg;
#pragma unroll
            for (int half = 0; half < 2; half++) {
                int row = r0 + half * 8;
                if (row >= M) continue;
                float vL = acc[mi][ni][half * 2 + 0] + bi.x;
                float vH = acc[mi][ni][half * 2 + 1] + bi.y;
                if (MODE == 1) {
                    float tL = fmaxf(fmaf(vL, scL, shL), 0.f);
                    float tH = fmaxf(fmaf(vH, scH, shH), 0.f);
                    unsigned hp, lp; split2(tL, tH, hp, lp);
                    long pidx = (long)row * (N >> 1) + (c >> 1);
                    CHi[pidx] = hp; CLo[pidx] = lp;
                } else if (MODE == 2) {
                    float2* p = reinterpret_cast<float2*>(C + (long)row * N + c);
                    float2 old = *p;
                    *p = make_float2(old.x + vL, old.y + vH);
                } else if (MODE == 3) {
                    float2* p = reinterpret_cast<float2*>(C + (long)row * N + c);
                    float2 old = *p;
                    float hL = old.x + vL, hH = old.y + vH;
                    *p = make_float2(hL, hH);
                    *reinterpret_cast<float2*>(R + (long)row * N + c) = make_float2(
                        fmaxf(fmaf(hL, scL, shL), 0.f), fmaxf(fmaf(hH, scH, shH), 0.f));
                } else { // MODE 4
                    *reinterpret_cast<float2*>(C + (long)row * N + c) = make_float2(vL, vH);
                    *reinterpret_cast<float2*>(R + (long)row * N + c) = make_float2(
                        fmaxf(fmaf(vL, scL, shL), 0.f), fmaxf(fmaf(vH, scH, shH), 0.f));
                }
            }
        }
    }
#undef AHS
#undef ALS
#undef BHS
#undef BLS
}

// ---------------------------------------------------------------------------
#define POOL_CHUNK 64
__global__ void pool_kernel(const int* __restrict__ batch,
                            const float* __restrict__ gg,
                            const float* __restrict__ gb,
                            const float* __restrict__ gm,
                            const float* __restrict__ gv)
{
    int c = threadIdx.x;
    int n0 = blockIdx.x * POOL_CHUNK;
    int n1 = min(n0 + POOL_CHUNK, N_NODES);
    float sc = gg[c] * rsqrtf(gv[c] + EPS_BN);
    float sh = gb[c] - gm[c] * sc;

    int curg = batch[n0];
    float acc = 0.f, cnt = 0.f;
    for (int n = n0; n < n1; n++) {
        int bg = batch[n];
        float val = fmaxf(fmaf(g_h[(long)n * H + c], sc, sh), 0.f);
        if (bg != curg) {
            atomicAdd(&g_pool[curg * H + c], acc);
            if (c == 0) atomicAdd(&g_cnt[curg], cnt);
            acc = 0.f; cnt = 0.f; curg = bg;
        }
        acc += val; cnt += 1.f;
    }
    atomicAdd(&g_pool[curg * H + c], acc);
    if (c == 0) atomicAdd(&g_cnt[curg], cnt);
}

__global__ void cls_kernel(const float* __restrict__ clinical,
                           const float* __restrict__ cw,
                           const float* __restrict__ cb,
                           float* __restrict__ out)
{
    int tid = threadIdx.x;
    if (tid >= NGRAPH * NCLS) return;
    int g = tid >> 1;
    int c = tid & 1;
    float inv = 1.f / fmaxf(g_cnt[g], 1.f);
    float acc = cb[c];
    for (int j = 0; j < H; j++)
        acc += g_pool[g * H + j] * inv * cw[j * NCLS + c];
    for (int k = 0; k < KCLIN; k++)
        acc += clinical[g * KCLIN + k] * cw[(H + k) * NCLS + c];
    out[g * NCLS + c] = acc;
}

// ---------------------------------------------------------------------------
extern "C" void kernel_launch(void* const* d_in, const int* in_sizes, int n_in,
                              void* d_out, int out_size)
{
    const float* x        = (const float*)d_in[0];
    const int*   ei       = (const int*)  d_in[1];
    const float* eattr    = (const float*)d_in[2];
    const int*   batch    = (const int*)  d_in[3];
    const float* clinical = (const float*)d_in[4];
    const float* lsw = (const float*)d_in[5],  *lsb = (const float*)d_in[6];
    const float* ldw = (const float*)d_in[7],  *ldb = (const float*)d_in[8];
    const float* ew  = (const float*)d_in[9],  *ebp = (const float*)d_in[10];
    const float* t   = (const float*)d_in[11];
    const float* w1  = (const float*)d_in[12], *b1  = (const float*)d_in[13];
    const float* bg  = (const float*)d_in[14], *bb  = (const float*)d_in[15];
    const float* bm  = (const float*)d_in[16], *bv  = (const float*)d_in[17];
    const float* w2  = (const float*)d_in[18], *b2  = (const float*)d_in[19];
    const float* ng  = (const float*)d_in[20], *nb  = (const float*)d_in[21];
    const float* nm  = (const float*)d_in[22], *nv  = (const float*)d_in[23];
    const float* cw  = (const float*)d_in[24], *cb  = (const float*)d_in[25];
    float* out = (float*)d_out;

    const int* src = ei;
    const int* dstp = ei + N_EDGES;

    float *xsd, *xsr, *hbuf, *bias0;
    unsigned *obh, *obl, *mdh, *mdl, *B0h, *B0l, *W1h, *W1l, *W2h, *W2l;
    cudaGetSymbolAddress((void**)&xsd,  g_xsd);
    cudaGetSymbolAddress((void**)&xsr,  g_xs);
    cudaGetSymbolAddress((void**)&hbuf, g_h);
    cudaGetSymbolAddress((void**)&obh,  g_obufh);
    cudaGetSymbolAddress((void**)&obl,  g_obufl);
    cudaGetSymbolAddress((void**)&mdh,  g_midh);
    cudaGetSymbolAddress((void**)&mdl,  g_midl);
    cudaGetSymbolAddress((void**)&B0h,  g_B0h);
    cudaGetSymbolAddress((void**)&B0l,  g_B0l);
    cudaGetSymbolAddress((void**)&W1h,  g_W1h);
    cudaGetSymbolAddress((void**)&W1l,  g_W1l);
    cudaGetSymbolAddress((void**)&W2h,  g_W2h);
    cudaGetSymbolAddress((void**)&W2l,  g_W2l);
    cudaGetSymbolAddress((void**)&bias0, g_bias0);

    static bool attr_done = false;
    if (!attr_done) {
        cudaFuncSetAttribute(bgemm_pipe<1>, cudaFuncAttributeMaxDynamicSharedMemorySize, PIPE_SMEM);
        cudaFuncSetAttribute(bgemm_pipe<2>, cudaFuncAttributeMaxDynamicSharedMemorySize, PIPE_SMEM);
        cudaFuncSetAttribute(bgemm_pipe<3>, cudaFuncAttributeMaxDynamicSharedMemorySize, PIPE_SMEM);
        cudaFuncSetAttribute(bgemm_pipe<4>, cudaFuncAttributeMaxDynamicSharedMemorySize, PIPE_SMEM);
        attr_done = true;
    }

    dim3 grid1((N_NODES + 127) / 128, 1);
    dim3 grid2((N_NODES + 127) / 128, 2);

    // Launches 1-5: pack + CSR scan front half
    pack_all<<<512, 256>>>(lsw, ldw, lsb, ldb, w1, w2);
    hist_kernel<<<(N_EDGES + 255) / 256, 256>>>(dstp);
    scan_local_kernel<<<SCAN_NB, SCAN_B>>>();
    scan_bsum_kernel<<<1, 128>>>();
    scan_add_kernel<<<(N_NODES + 255) / 256, 256>>>();

    // Launch 6 (profiled by -s 5 -c 1): input projection GEMM
    bgemm_fp32<<<grid2, 256>>>(x, B0h, B0l, bias0, xsd, N_NODES, 256, 256);

    scatter_kernel<<<(N_EDGES + 255) / 256, 256>>>(src, dstp, eattr);

    for (int l = 0; l < NLAYERS; l++) {
        if (l == 0)
            gather_kernel<<<(N_NODES * 32 + 255) / 256, 256>>>(
                xsd, 256, xsd + 128, ew + l * H, ebp + l * H, t, l);
        else
            gather_kernel<<<(N_NODES * 32 + 255) / 256, 256>>>(
                xsr, 128, xsr, ew + l * H, ebp + l * H, t, l);

        // mid = split(relu(bn(obuf @ w1 + b1)))
        bgemm_pipe<1><<<grid2, 256, PIPE_SMEM>>>(obh, obl,
                                                 W1h + l * 16384, W1l + l * 16384,
                                                 b1 + l * H2,
                                                 nullptr, mdh, mdl, nullptr,
                                                 N_NODES, H2, H,
                                                 bg + l * H2, bb + l * H2,
                                                 bm + l * H2, bv + l * H2);

        if (l == 0)
            bgemm_pipe<4><<<grid1, 256, PIPE_SMEM>>>(mdh, mdl,
                                                     W2h + l * 16384, W2l + l * 16384,
                                                     b2 + l * H,
                                                     hbuf, nullptr, nullptr, xsr,
                                                     N_NODES, H, H2,
                                                     ng + (l + 1) * H, nb + (l + 1) * H,
                                                     nm + (l + 1) * H, nv + (l + 1) * H);
        else if (l < NLAYERS - 1)
            bgemm_pipe<3><<<grid1, 256, PIPE_SMEM>>>(mdh, mdl,
                                                     W2h + l * 16384, W2l + l * 16384,
                                                     b2 + l * H,
                                                     hbuf, nullptr, nullptr, xsr,
                                                     N_NODES, H, H2,
                                                     ng + (l + 1) * H, nb + (l + 1) * H,
                                                     nm + (l + 1) * H, nv + (l + 1) * H);
        else
            bgemm_pipe<2><<<grid1, 256, PIPE_SMEM>>>(mdh, mdl,
                                                     W2h + l * 16384, W2l + l * 16384,
                                                     b2 + l * H,
                                                     hbuf, nullptr, nullptr, nullptr,
                                                     N_NODES, H, H2,
                                                     nullptr, nullptr, nullptr, nullptr);
    }

    pool_kernel<<<(N_NODES + POOL_CHUNK - 1) / POOL_CHUNK, H>>>(batch, ng, nb, nm, nv);
    cls_kernel<<<1, 128>>>(clinical, cw, cb, out);
}

// round 7
// speedup vs baseline: 3.9375x; 1.1192x over previous
#include <cuda_runtime.h>
#include <math.h>

// Problem dims (fixed by dataset)
#define N_NODES 50000
#define N_EDGES 500000
#define C_IN    256
#define H       128
#define H2      256
#define NLAYERS 4
#define NGRAPH  64
#define KCLIN   8
#define NCLS    2
#define EPS_MSG 1e-7f
#define EPS_BN  1e-5f

#define SCAN_B  512
#define SCAN_NB ((N_NODES + SCAN_B - 1) / SCAN_B)   // 98
#define SMS 136    // B smem row stride in words (mod 32 == 8 -> conflict-free)
#define ASTRIDE 20 // A stage row stride (mod 32 == 20 but pattern 4*tg+tq ok? see note)
#define MIDSTRIDE 132 // mid row stride (mod 32 == 4 -> 4*tg+tq distinct)

// ---------------------------------------------------------------------------
// Scratch (device globals; no allocation allowed)
// ---------------------------------------------------------------------------
__device__ float    g_xsd [N_NODES * 256];   // layer-0 src|dst projections
__device__ float    g_xs  [N_NODES * H];     // r buffer (layers >= 1)
__device__ float    g_h   [N_NODES * H];
__device__ unsigned g_obufh[N_NODES * 64];   // gather out, packed bf16x2 hi
__device__ unsigned g_obufl[N_NODES * 64];
__device__ unsigned g_xh  [N_NODES * 128];   // x pre-split packed
__device__ unsigned g_xl  [N_NODES * 128];
__device__ float    g_pool[NGRAPH * H];
__device__ float    g_cnt [NGRAPH];

// Pre-split weights (packed bf16x2 pairs along K)
__device__ unsigned g_B0h[128 * 256], g_B0l[128 * 256];
__device__ float    g_bias0[256];
__device__ unsigned g_W1h[NLAYERS * 64 * 256], g_W1l[NLAYERS * 64 * 256];
__device__ unsigned g_W2h[NLAYERS * 128 * 128], g_W2l[NLAYERS * 128 * 128];

// CSR build scratch
__device__ int  g_count[N_NODES];
__device__ int  g_row  [N_NODES + 1];
__device__ int  g_bsum [128];
__device__ int2 g_edges[N_EDGES];

// ---------------------------------------------------------------------------
// helpers
// ---------------------------------------------------------------------------
__device__ __forceinline__ unsigned packbf(float lo, float hi) {
    unsigned r;
    asm("cvt.rn.bf16x2.f32 %0, %1, %2;" : "=r"(r) : "f"(hi), "f"(lo));
    return r;
}
__device__ __forceinline__ float2 unpackbf(unsigned p) {
    float2 f;
    f.x = __uint_as_float(p << 16);
    f.y = __uint_as_float(p & 0xffff0000u);
    return f;
}
__device__ __forceinline__ void split2(float a, float b, unsigned& h, unsigned& l) {
    h = packbf(a, b);
    float2 f = unpackbf(h);
    l = packbf(a - f.x, b - f.y);
}
__device__ __forceinline__ void mma_bf16(float c[4],
                                         unsigned a0, unsigned a1, unsigned a2, unsigned a3,
                                         unsigned b0, unsigned b1) {
    asm volatile(
        "mma.sync.aligned.m16n8k16.row.col.f32.bf16.bf16.f32 "
        "{%0,%1,%2,%3}, {%4,%5,%6,%7}, {%8,%9}, {%0,%1,%2,%3};"
        : "+f"(c[0]), "+f"(c[1]), "+f"(c[2]), "+f"(c[3])
        : "r"(a0), "r"(a1), "r"(a2), "r"(a3), "r"(b0), "r"(b1));
}
__device__ __forceinline__ void cp_async8(void* smem, const void* gmem, bool pred) {
    unsigned sa = (unsigned)__cvta_generic_to_shared(smem);
    int sz = pred ? 8 : 0;
    asm volatile("cp.async.ca.shared.global [%0], [%1], 8, %2;\n"
                 :: "r"(sa), "l"(gmem), "r"(sz));
}
__device__ __forceinline__ void cp_async16(void* smem, const void* gmem) {
    unsigned sa = (unsigned)__cvta_generic_to_shared(smem);
    asm volatile("cp.async.cg.shared.global [%0], [%1], 16;\n"
                 :: "r"(sa), "l"(gmem));
}
__device__ __forceinline__ void cp_commit() {
    asm volatile("cp.async.commit_group;\n" ::);
}
template<int W> __device__ __forceinline__ void cp_wait() {
    asm volatile("cp.async.wait_group %0;\n" :: "n"(W));
}

// ---------------------------------------------------------------------------
// pack_all: zero accumulators + pre-split all weights (one launch)
// ---------------------------------------------------------------------------
__global__ void pack_all(const float* __restrict__ lsw, const float* __restrict__ ldw,
                         const float* __restrict__ lsb, const float* __restrict__ ldb,
                         const float* __restrict__ w1, const float* __restrict__ w2)
{
    int i = blockIdx.x * blockDim.x + threadIdx.x;
    int stride = gridDim.x * blockDim.x;
    for (int k = i; k < N_NODES; k += stride) g_count[k] = 0;
    if (i < NGRAPH * H) g_pool[i] = 0.f;
    if (i < NGRAPH) g_cnt[i] = 0.f;
    if (i < 256) g_bias0[i] = (i < 128) ? lsb[i] : ldb[i - 128];

    for (int idx = i; idx < 128 * 256; idx += stride) {
        int k2 = idx >> 8, n = idx & 255;
        float v0, v1;
        if (n < 128) { v0 = lsw[(2*k2)*128 + n];       v1 = lsw[(2*k2+1)*128 + n]; }
        else         { v0 = ldw[(2*k2)*128 + n - 128]; v1 = ldw[(2*k2+1)*128 + n - 128]; }
        unsigned h, l; split2(v0, v1, h, l);
        g_B0h[idx] = h; g_B0l[idx] = l;
    }
    for (int idx = i; idx < NLAYERS * 64 * 256; idx += stride) {
        int l = idx >> 14, rem = idx & 16383;
        int k2 = rem >> 8, n = rem & 255;
        const float* base = w1 + (long)l * 128 * 256;
        unsigned h, lo; split2(base[(2*k2)*256 + n], base[(2*k2+1)*256 + n], h, lo);
        g_W1h[idx] = h; g_W1l[idx] = lo;
    }
    for (int idx = i; idx < NLAYERS * 128 * 128; idx += stride) {
        int l = idx >> 14, rem = idx & 16383;
        int k2 = rem >> 7, n = rem & 127;
        const float* base = w2 + (long)l * 256 * 128;
        unsigned h, lo; split2(base[(2*k2)*128 + n], base[(2*k2+1)*128 + n], h, lo);
        g_W2h[idx] = h; g_W2l[idx] = lo;
    }
}

// pack_x: pre-split node features into packed bf16x2 hi/lo
__global__ void pack_x(const float* __restrict__ x) {
    int idx = blockIdx.x * blockDim.x + threadIdx.x;
    if (idx >= N_NODES * 128) return;
    int row = idx >> 7, k2 = idx & 127;
    float2 v = *reinterpret_cast<const float2*>(x + (long)row * 256 + 2 * k2);
    unsigned h, l; split2(v.x, v.y, h, l);
    g_xh[idx] = h; g_xl[idx] = l;
}

// ---------------------------------------------------------------------------
// CSR build
// ---------------------------------------------------------------------------
__global__ void hist_kernel(const int* __restrict__ dst) {
    int i = blockIdx.x * blockDim.x + threadIdx.x;
    if (i < N_EDGES) atomicAdd(&g_count[dst[i]], 1);
}

__global__ void scan_local_kernel() {
    __shared__ int sh[SCAN_B];
    int tid = threadIdx.x;
    int i = blockIdx.x * SCAN_B + tid;
    int v = (i < N_NODES) ? g_count[i] : 0;
    sh[tid] = v;
    __syncthreads();
    for (int off = 1; off < SCAN_B; off <<= 1) {
        int t = (tid >= off) ? sh[tid - off] : 0;
        __syncthreads();
        sh[tid] += t;
        __syncthreads();
    }
    if (i < N_NODES) g_row[i] = sh[tid] - v;
    if (tid == SCAN_B - 1) g_bsum[blockIdx.x] = sh[tid];
}

__global__ void scan_bsum_kernel() {
    __shared__ int sh[128];
    int tid = threadIdx.x;
    int v = (tid < SCAN_NB) ? g_bsum[tid] : 0;
    sh[tid] = v;
    __syncthreads();
    for (int off = 1; off < 128; off <<= 1) {
        int t = (tid >= off) ? sh[tid - off] : 0;
        __syncthreads();
        sh[tid] += t;
        __syncthreads();
    }
    if (tid < SCAN_NB) g_bsum[tid] = sh[tid] - v;
}

__global__ void scan_add_kernel() {
    int i = blockIdx.x * blockDim.x + threadIdx.x;
    if (i < N_NODES) {
        int r = g_row[i] + g_bsum[i / SCAN_B];
        g_row[i] = r;
        g_count[i] = r;
    }
    if (i == 0) g_row[N_NODES] = N_EDGES;
}

__global__ void scatter_kernel(const int* __restrict__ src,
                               const int* __restrict__ dst,
                               const float* __restrict__ eattr) {
    int e = blockIdx.x * blockDim.x + threadIdx.x;
    if (e >= N_EDGES) return;
    int d = dst[e];
    int pos = atomicAdd(&g_count[d], 1);
    g_edges[pos] = make_int2(src[e], __float_as_int(eattr[e]));
}

// ---------------------------------------------------------------------------
// Gather: one warp per dst node; softmax aggregation without max-shift.
// Emits packed bf16x2 hi/lo for the following MLP.
// ---------------------------------------------------------------------------
__global__ __launch_bounds__(256)
void gather_kernel(const float* __restrict__ xs, int ldx,
                   const float* __restrict__ xd,
                   const float* __restrict__ ew,
                   const float* __restrict__ eb,
                   const float* __restrict__ tptr, int l)
{
    int warp = (blockIdx.x * blockDim.x + threadIdx.x) >> 5;
    if (warp >= N_NODES) return;
    int lane = threadIdx.x & 31;
    int c0 = lane * 4;

    float4 w4 = *reinterpret_cast<const float4*>(ew + c0);
    float4 b4 = *reinterpret_cast<const float4*>(eb + c0);
    float tv = tptr[l];

    int e0 = g_row[warp];
    int e1 = g_row[warp + 1];

    float n0 = 0.f, n1 = 0.f, n2 = 0.f, n3 = 0.f;
    float d0 = 0.f, d1 = 0.f, d2 = 0.f, d3 = 0.f;

#pragma unroll 4
    for (int e = e0; e < e1; e++) {
        int2 ed = g_edges[e];
        int   s  = ed.x;
        float al = __int_as_float(ed.y);
        float4 x4 = *reinterpret_cast<const float4*>(xs + (long)s * ldx + c0);

        float m0 = fmaxf(fmaf(al, w4.x, b4.x) + x4.x, 0.f) + EPS_MSG;
        float m1 = fmaxf(fmaf(al, w4.y, b4.y) + x4.y, 0.f) + EPS_MSG;
        float m2 = fmaxf(fmaf(al, w4.z, b4.z) + x4.z, 0.f) + EPS_MSG;
        float m3 = fmaxf(fmaf(al, w4.w, b4.w) + x4.w, 0.f) + EPS_MSG;

        float z0 = __expf(m0 * tv);
        float z1 = __expf(m1 * tv);
        float z2 = __expf(m2 * tv);
        float z3 = __expf(m3 * tv);

        d0 += z0; d1 += z1; d2 += z2; d3 += z3;
        n0 = fmaf(m0, z0, n0); n1 = fmaf(m1, z1, n1);
        n2 = fmaf(m2, z2, n2); n3 = fmaf(m3, z3, n3);
    }

    float4 xv = *reinterpret_cast<const float4*>(xd + (long)warp * ldx + c0);
    float ox = n0 / fmaxf(d0, 1e-16f) + xv.x;
    float oy = n1 / fmaxf(d1, 1e-16f) + xv.y;
    float oz = n2 / fmaxf(d2, 1e-16f) + xv.z;
    float ow = n3 / fmaxf(d3, 1e-16f) + xv.w;

    unsigned h0, l0, h1, l1;
    split2(ox, oy, h0, l0);
    split2(oz, ow, h1, l1);
    int p = warp * 64 + (c0 >> 1);
    *reinterpret_cast<uint2*>(g_obufh + p) = make_uint2(h0, h1);
    *reinterpret_cast<uint2*>(g_obufl + p) = make_uint2(l0, l1);
}

// ---------------------------------------------------------------------------
// Pipelined GEMM (pre-split packed A) with cp.async double buffering.
// MODE 0: C = v (fp32). Used for the input projection.
// ---------------------------------------------------------------------------
#define PIPE_SMEM ((2*128*ASTRIDE*2 + 2*16*SMS*2) * 4)

__global__ __launch_bounds__(256)
void bgemm_pipe0(const unsigned* __restrict__ Ah_g, const unsigned* __restrict__ Al_g,
                 const unsigned* __restrict__ Bh_g, const unsigned* __restrict__ Bl_g,
                 const float* __restrict__ bias, float* __restrict__ C,
                 int M, int N, int K)
{
    extern __shared__ unsigned smem_[];
    unsigned* Ah = smem_;
    unsigned* Al = Ah + 2 * 128 * ASTRIDE;
    unsigned* Bh = Al + 2 * 128 * ASTRIDE;
    unsigned* Bl = Bh + 2 * 16 * SMS;
#define AHS(s,r,k) Ah[((s)*128 + (r)) * ASTRIDE + (k)]
#define ALS(s,r,k) Al[((s)*128 + (r)) * ASTRIDE + (k)]
#define BHS(s,r,n) Bh[((s)*16 + (r)) * SMS + (n)]
#define BLS(s,r,n) Bl[((s)*16 + (r)) * SMS + (n)]

    int tid = threadIdx.x;
    int wid = tid >> 5, lane = tid & 31;
    int tg = lane >> 2, tq = lane & 3;
    int warpM = wid >> 2, warpN = wid & 3;
    int rowBase = blockIdx.x * 128;
    int colBase = blockIdx.y * 128;
    int mW = warpM * 64, nW = warpN * 32;
    int K2 = K >> 1;

    float acc[4][4][4];
#pragma unroll
    for (int mi = 0; mi < 4; mi++)
#pragma unroll
        for (int ni = 0; ni < 4; ni++)
#pragma unroll
            for (int r = 0; r < 4; r++) acc[mi][ni][r] = 0.f;

    auto load_stage = [&](int s, int k0) {
        int k20 = k0 >> 1;
#pragma unroll
        for (int i = 0; i < 4; i++) {
            int idx = tid + i * 256;
            int r = idx >> 3;
            int kc2 = (idx & 7) * 2;
            int gr = rowBase + r;
            bool ok = gr < M;
            long off = (long)(ok ? gr : 0) * K2 + k20 + kc2;
            cp_async8(&AHS(s, r, kc2), Ah_g + off, ok);
            cp_async8(&ALS(s, r, kc2), Al_g + off, ok);
        }
#pragma unroll
        for (int i = 0; i < 2; i++) {
            int idx = tid + i * 256;
            int kr = idx >> 5;
            int nc = (idx & 31) * 4;
            long off = (long)(k20 + kr) * N + colBase + nc;
            cp_async16(&BHS(s, kr, nc), Bh_g + off);
            cp_async16(&BLS(s, kr, nc), Bl_g + off);
        }
        cp_commit();
    };

    int nIter = K >> 5;
    load_stage(0, 0);

    for (int it = 0; it < nIter; it++) {
        if (it + 1 < nIter) {
            load_stage((it + 1) & 1, (it + 1) << 5);
            cp_wait<1>();
        } else {
            cp_wait<0>();
        }
        __syncthreads();

        int s = it & 1;
#pragma unroll
        for (int kk = 0; kk < 2; kk++) {
            int k2a = kk * 8 + tq, k2b = k2a + 4;
            unsigned bh0[4], bh1[4], bl0[4], bl1[4];
#pragma unroll
            for (int ni = 0; ni < 4; ni++) {
                int n = nW + ni * 8 + tg;
                bh0[ni] = BHS(s, k2a, n); bh1[ni] = BHS(s, k2b, n);
                bl0[ni] = BLS(s, k2a, n); bl1[ni] = BLS(s, k2b, n);
            }
#pragma unroll
            for (int mi = 0; mi < 4; mi++) {
                int m = mW + mi * 16 + tg;
                unsigned ah0 = AHS(s, m, k2a), ah1 = AHS(s, m + 8, k2a);
                unsigned ah2 = AHS(s, m, k2b), ah3 = AHS(s, m + 8, k2b);
                unsigned al0 = ALS(s, m, k2a), al1 = ALS(s, m + 8, k2a);
                unsigned al2 = ALS(s, m, k2b), al3 = ALS(s, m + 8, k2b);
#pragma unroll
                for (int ni = 0; ni < 4; ni++) {
                    mma_bf16(acc[mi][ni], ah0, ah1, ah2, ah3, bh0[ni], bh1[ni]);
                    mma_bf16(acc[mi][ni], ah0, ah1, ah2, ah3, bl0[ni], bl1[ni]);
                    mma_bf16(acc[mi][ni], al0, al1, al2, al3, bh0[ni], bh1[ni]);
                }
            }
        }
        __syncthreads();
    }

#pragma unroll
    for (int ni = 0; ni < 4; ni++) {
        int c = colBase + nW + ni * 8 + tq * 2;
        float2 bi = *reinterpret_cast<const float2*>(bias + c);
#pragma unroll
        for (int mi = 0; mi < 4; mi++) {
            int r0 = rowBase + mW + mi * 16 + tg;
#pragma unroll
            for (int half = 0; half < 2; half++) {
                int row = r0 + half * 8;
                if (row >= M) continue;
                float vL = acc[mi][ni][half * 2 + 0] + bi.x;
                float vH = acc[mi][ni][half * 2 + 1] + bi.y;
                *reinterpret_cast<float2*>(C + (long)row * N + c) = make_float2(vL, vH);
            }
        }
    }
#undef AHS
#undef ALS
#undef BHS
#undef BLS
}

// ---------------------------------------------------------------------------
// Fused MLP: per 128-node tile computes
//   mid = split(relu(bn(obuf @ W1 + b1)))   (mid resident in smem)
//   v   = mid @ W2 + b2
//   MODE 4: h  = v; R = relu(bn_next(h))
//   MODE 3: h += v; R = relu(bn_next(h))
//   MODE 2: h += v
// smem: A stages (2x128x20 x2) + B stages (2x16x136 x2) + mid (128x132 x2)
// ---------------------------------------------------------------------------
#define FUSED_SMEM ((2*128*ASTRIDE*2 + 2*16*SMS*2 + 128*MIDSTRIDE*2) * 4)

template<int MODE>
__global__ __launch_bounds__(256)
void fused_mlp(const unsigned* __restrict__ Ah_g, const unsigned* __restrict__ Al_g,
               const unsigned* __restrict__ W1h_g, const unsigned* __restrict__ W1l_g,
               const unsigned* __restrict__ W2h_g, const unsigned* __restrict__ W2l_g,
               const float* __restrict__ b1,
               const float* __restrict__ bnAg, const float* __restrict__ bnAb,
               const float* __restrict__ bnAm, const float* __restrict__ bnAv,
               const float* __restrict__ b2,
               float* __restrict__ C, float* __restrict__ R,
               const float* __restrict__ bnNg, const float* __restrict__ bnNb,
               const float* __restrict__ bnNm, const float* __restrict__ bnNv,
               int M)
{
    extern __shared__ unsigned smem_[];
    unsigned* Ah = smem_;                          // [2][128][ASTRIDE]
    unsigned* Al = Ah + 2 * 128 * ASTRIDE;
    unsigned* Bh = Al + 2 * 128 * ASTRIDE;         // [2][16][SMS]
    unsigned* Bl = Bh + 2 * 16 * SMS;
    unsigned* MidH = Bl + 2 * 16 * SMS;            // [128][MIDSTRIDE]
    unsigned* MidL = MidH + 128 * MIDSTRIDE;
#define AHS(s,r,k) Ah[((s)*128 + (r)) * ASTRIDE + (k)]
#define ALS(s,r,k) Al[((s)*128 + (r)) * ASTRIDE + (k)]
#define BHS(s,r,n) Bh[((s)*16 + (r)) * SMS + (n)]
#define BLS(s,r,n) Bl[((s)*16 + (r)) * SMS + (n)]
#define MIDH(r,k)  MidH[(r) * MIDSTRIDE + (k)]
#define MIDL(r,k)  MidL[(r) * MIDSTRIDE + (k)]

    int tid = threadIdx.x;
    int wid = tid >> 5, lane = tid & 31;
    int tg = lane >> 2, tq = lane & 3;
    int warpM = wid >> 2, warpN = wid & 3;
    int rowBase = blockIdx.x * 128;
    int mW = warpM * 64, nW = warpN * 32;

    float acc[4][4][4];

    // ---------------- Phase A: mid = split(relu(bn(obuf @ W1 + b1))) --------
    // obuf: [M][64] packed (K=128). W1: [64][256]. Two column halves of 128.
    for (int halfN = 0; halfN < 2; halfN++) {
        int colBase = halfN * 128;
#pragma unroll
        for (int mi = 0; mi < 4; mi++)
#pragma unroll
            for (int ni = 0; ni < 4; ni++)
#pragma unroll
                for (int r = 0; r < 4; r++) acc[mi][ni][r] = 0.f;

        auto load_stageA = [&](int s, int k20) {
#pragma unroll
            for (int i = 0; i < 4; i++) {
                int idx = tid + i * 256;
                int r = idx >> 3;
                int kc2 = (idx & 7) * 2;
                int gr = rowBase + r;
                bool ok = gr < M;
                long off = (long)(ok ? gr : 0) * 64 + k20 + kc2;
                cp_async8(&AHS(s, r, kc2), Ah_g + off, ok);
                cp_async8(&ALS(s, r, kc2), Al_g + off, ok);
            }
#pragma unroll
            for (int i = 0; i < 2; i++) {
                int idx = tid + i * 256;
                int kr = idx >> 5;
                int nc = (idx & 31) * 4;
                long off = (long)(k20 + kr) * 256 + colBase + nc;
                cp_async16(&BHS(s, kr, nc), W1h_g + off);
                cp_async16(&BLS(s, kr, nc), W1l_g + off);
            }
            cp_commit();
        };

        load_stageA(0, 0);
        for (int it = 0; it < 4; it++) {
            if (it + 1 < 4) { load_stageA((it + 1) & 1, (it + 1) * 16); cp_wait<1>(); }
            else            { cp_wait<0>(); }
            __syncthreads();
            int s = it & 1;
#pragma unroll
            for (int kk = 0; kk < 2; kk++) {
                int k2a = kk * 8 + tq, k2b = k2a + 4;
                unsigned bh0[4], bh1[4], bl0[4], bl1[4];
#pragma unroll
                for (int ni = 0; ni < 4; ni++) {
                    int n = nW + ni * 8 + tg;
                    bh0[ni] = BHS(s, k2a, n); bh1[ni] = BHS(s, k2b, n);
                    bl0[ni] = BLS(s, k2a, n); bl1[ni] = BLS(s, k2b, n);
                }
#pragma unroll
                for (int mi = 0; mi < 4; mi++) {
                    int m = mW + mi * 16 + tg;
                    unsigned ah0 = AHS(s, m, k2a), ah1 = AHS(s, m + 8, k2a);
                    unsigned ah2 = AHS(s, m, k2b), ah3 = AHS(s, m + 8, k2b);
                    unsigned al0 = ALS(s, m, k2a), al1 = ALS(s, m + 8, k2a);
                    unsigned al2 = ALS(s, m, k2b), al3 = ALS(s, m + 8, k2b);
#pragma unroll
                    for (int ni = 0; ni < 4; ni++) {
                        mma_bf16(acc[mi][ni], ah0, ah1, ah2, ah3, bh0[ni], bh1[ni]);
                        mma_bf16(acc[mi][ni], ah0, ah1, ah2, ah3, bl0[ni], bl1[ni]);
                        mma_bf16(acc[mi][ni], al0, al1, al2, al3, bh0[ni], bh1[ni]);
                    }
                }
            }
            __syncthreads();
        }

        // epilogue -> mid smem (bn + relu + split)
#pragma unroll
        for (int ni = 0; ni < 4; ni++) {
            int c = colBase + nW + ni * 8 + tq * 2;
            float2 bi = *reinterpret_cast<const float2*>(b1 + c);
            float2 gg = *reinterpret_cast<const float2*>(bnAg + c);
            float2 gb = *reinterpret_cast<const float2*>(bnAb + c);
            float2 gm = *reinterpret_cast<const float2*>(bnAm + c);
            float2 gv = *reinterpret_cast<const float2*>(bnAv + c);
            float scL = gg.x * rsqrtf(gv.x + EPS_BN), shL = gb.x - gm.x * scL;
            float scH = gg.y * rsqrtf(gv.y + EPS_BN), shH = gb.y - gm.y * scH;
            int pcol = c >> 1;
#pragma unroll
            for (int mi = 0; mi < 4; mi++) {
#pragma unroll
                for (int hr = 0; hr < 2; hr++) {
                    int rl = mW + mi * 16 + tg + hr * 8;
                    float vL = acc[mi][ni][hr * 2 + 0] + bi.x;
                    float vH = acc[mi][ni][hr * 2 + 1] + bi.y;
                    float tL = fmaxf(fmaf(vL, scL, shL), 0.f);
                    float tH = fmaxf(fmaf(vH, scH, shH), 0.f);
                    unsigned hp, lp; split2(tL, tH, hp, lp);
                    MIDH(rl, pcol) = hp;
                    MIDL(rl, pcol) = lp;
                }
            }
        }
        __syncthreads();
    }

    // ---------------- Phase B: v = mid @ W2 + b2 ---------------------------
    // mid: smem [128 rows][128 k2]. W2: [128 k2][128]. N=128, colBase=0.
#pragma unroll
    for (int mi = 0; mi < 4; mi++)
#pragma unroll
        for (int ni = 0; ni < 4; ni++)
#pragma unroll
            for (int r = 0; r < 4; r++) acc[mi][ni][r] = 0.f;

    auto load_stageB = [&](int s, int k20) {
#pragma unroll
        for (int i = 0; i < 2; i++) {
            int idx = tid + i * 256;
            int kr = idx >> 5;
            int nc = (idx & 31) * 4;
            long off = (long)(k20 + kr) * 128 + nc;
            cp_async16(&BHS(s, kr, nc), W2h_g + off);
            cp_async16(&BLS(s, kr, nc), W2l_g + off);
        }
        cp_commit();
    };

    load_stageB(0, 0);
    for (int it = 0; it < 8; it++) {
        if (it + 1 < 8) { load_stageB((it + 1) & 1, (it + 1) * 16); cp_wait<1>(); }
        else            { cp_wait<0>(); }
        __syncthreads();
        int s = it & 1;
#pragma unroll
        for (int kk = 0; kk < 2; kk++) {
            int k2a = kk * 8 + tq, k2b = k2a + 4;       // within stage
            int g2a = it * 16 + k2a, g2b = it * 16 + k2b; // global k2 for mid
            unsigned bh0[4], bh1[4], bl0[4], bl1[4];
#pragma unroll
            for (int ni = 0; ni < 4; ni++) {
                int n = nW + ni * 8 + tg;
                bh0[ni] = BHS(s, k2a, n); bh1[ni] = BHS(s, k2b, n);
                bl0[ni] = BLS(s, k2a, n); bl1[ni] = BLS(s, k2b, n);
            }
#pragma unroll
            for (int mi = 0; mi < 4; mi++) {
                int m = mW + mi * 16 + tg;
                unsigned ah0 = MIDH(m, g2a), ah1 = MIDH(m + 8, g2a);
                unsigned ah2 = MIDH(m, g2b), ah3 = MIDH(m + 8, g2b);
                unsigned al0 = MIDL(m, g2a), al1 = MIDL(m + 8, g2a);
                unsigned al2 = MIDL(m, g2b), al3 = MIDL(m + 8, g2b);
#pragma unroll
                for (int ni = 0; ni < 4; ni++) {
                    mma_bf16(acc[mi][ni], ah0, ah1, ah2, ah3, bh0[ni], bh1[ni]);
                    mma_bf16(acc[mi][ni], ah0, ah1, ah2, ah3, bl0[ni], bl1[ni]);
                    mma_bf16(acc[mi][ni], al0, al1, al2, al3, bh0[ni], bh1[ni]);
                }
            }
        }
        __syncthreads();
    }

    // Final epilogue
#pragma unroll
    for (int ni = 0; ni < 4; ni++) {
        int c = nW + ni * 8 + tq * 2;
        float2 bi = *reinterpret_cast<const float2*>(b2 + c);
        float scL = 1.f, shL = 0.f, scH = 1.f, shH = 0.f;
        if (MODE == 3 || MODE == 4) {
            float2 gg = *reinterpret_cast<const float2*>(bnNg + c);
            float2 gb = *reinterpret_cast<const float2*>(bnNb + c);
            float2 gm = *reinterpret_cast<const float2*>(bnNm + c);
            float2 gv = *reinterpret_cast<const float2*>(bnNv + c);
            scL = gg.x * rsqrtf(gv.x + EPS_BN); shL = gb.x - gm.x * scL;
            scH = gg.y * rsqrtf(gv.y + EPS_BN); shH = gb.y - gm.y * scH;
        }
#pragma unroll
        for (int mi = 0; mi < 4; mi++) {
            int r0 = rowBase + mW + mi * 16 + tg;
#pragma unroll
            for (int hr = 0; hr < 2; hr++) {
                int row = r0 + hr * 8;
                if (row >= M) continue;
                float vL = acc[mi][ni][hr * 2 + 0] + bi.x;
                float vH = acc[mi][ni][hr * 2 + 1] + bi.y;
                float2* p = reinterpret_cast<float2*>(C + (long)row * 128 + c);
                if (MODE == 4) {
                    *p = make_float2(vL, vH);
                    *reinterpret_cast<float2*>(R + (long)row * 128 + c) = make_float2(
                        fmaxf(fmaf(vL, scL, shL), 0.f), fmaxf(fmaf(vH, scH, shH), 0.f));
                } else if (MODE == 3) {
                    float2 old = *p;
                    float hL = old.x + vL, hH = old.y + vH;
                    *p = make_float2(hL, hH);
                    *reinterpret_cast<float2*>(R + (long)row * 128 + c) = make_float2(
                        fmaxf(fmaf(hL, scL, shL), 0.f), fmaxf(fmaf(hH, scH, shH), 0.f));
                } else { // MODE 2
                    float2 old = *p;
                    *p = make_float2(old.x + vL, old.y + vH);
                }
            }
        }
    }
#undef AHS
#undef ALS
#undef BHS
#undef BLS
#undef MIDH
#undef MIDL
}

// ---------------------------------------------------------------------------
#define POOL_CHUNK 64
__global__ void pool_kernel(const int* __restrict__ batch,
                            const float* __restrict__ gg,
                            const float* __restrict__ gb,
                            const float* __restrict__ gm,
                            const float* __restrict__ gv)
{
    int c = threadIdx.x;
    int n0 = blockIdx.x * POOL_CHUNK;
    int n1 = min(n0 + POOL_CHUNK, N_NODES);
    float sc = gg[c] * rsqrtf(gv[c] + EPS_BN);
    float sh = gb[c] - gm[c] * sc;

    int curg = batch[n0];
    float acc = 0.f, cnt = 0.f;
    for (int n = n0; n < n1; n++) {
        int bg = batch[n];
        float val = fmaxf(fmaf(g_h[(long)n * H + c], sc, sh), 0.f);
        if (bg != curg) {
            atomicAdd(&g_pool[curg * H + c], acc);
            if (c == 0) atomicAdd(&g_cnt[curg], cnt);
            acc = 0.f; cnt = 0.f; curg = bg;
        }
        acc += val; cnt += 1.f;
    }
    atomicAdd(&g_pool[curg * H + c], acc);
    if (c == 0) atomicAdd(&g_cnt[curg], cnt);
}

__global__ void cls_kernel(const float* __restrict__ clinical,
                           const float* __restrict__ cw,
                           const float* __restrict__ cb,
                           float* __restrict__ out)
{
    int tid = threadIdx.x;
    if (tid >= NGRAPH * NCLS) return;
    int g = tid >> 1;
    int c = tid & 1;
    float inv = 1.f / fmaxf(g_cnt[g], 1.f);
    float acc = cb[c];
    for (int j = 0; j < H; j++)
        acc += g_pool[g * H + j] * inv * cw[j * NCLS + c];
    for (int k = 0; k < KCLIN; k++)
        acc += clinical[g * KCLIN + k] * cw[(H + k) * NCLS + c];
    out[g * NCLS + c] = acc;
}

// ---------------------------------------------------------------------------
extern "C" void kernel_launch(void* const* d_in, const int* in_sizes, int n_in,
                              void* d_out, int out_size)
{
    const float* x        = (const float*)d_in[0];
    const int*   ei       = (const int*)  d_in[1];
    const float* eattr    = (const float*)d_in[2];
    const int*   batch    = (const int*)  d_in[3];
    const float* clinical = (const float*)d_in[4];
    const float* lsw = (const float*)d_in[5],  *lsb = (const float*)d_in[6];
    const float* ldw = (const float*)d_in[7],  *ldb = (const float*)d_in[8];
    const float* ew  = (const float*)d_in[9],  *ebp = (const float*)d_in[10];
    const float* t   = (const float*)d_in[11];
    const float* w1  = (const float*)d_in[12], *b1  = (const float*)d_in[13];
    const float* bg  = (const float*)d_in[14], *bb  = (const float*)d_in[15];
    const float* bm  = (const float*)d_in[16], *bv  = (const float*)d_in[17];
    const float* w2  = (const float*)d_in[18], *b2  = (const float*)d_in[19];
    const float* ng  = (const float*)d_in[20], *nb  = (const float*)d_in[21];
    const float* nm  = (const float*)d_in[22], *nv  = (const float*)d_in[23];
    const float* cw  = (const float*)d_in[24], *cb  = (const float*)d_in[25];
    float* out = (float*)d_out;

    const int* src = ei;
    const int* dstp = ei + N_EDGES;

    float *xsd, *xsr, *hbuf, *bias0;
    unsigned *obh, *obl, *xh, *xl, *B0h, *B0l, *W1h, *W1l, *W2h, *W2l;
    cudaGetSymbolAddress((void**)&xsd,  g_xsd);
    cudaGetSymbolAddress((void**)&xsr,  g_xs);
    cudaGetSymbolAddress((void**)&hbuf, g_h);
    cudaGetSymbolAddress((void**)&obh,  g_obufh);
    cudaGetSymbolAddress((void**)&obl,  g_obufl);
    cudaGetSymbolAddress((void**)&xh,   g_xh);
    cudaGetSymbolAddress((void**)&xl,   g_xl);
    cudaGetSymbolAddress((void**)&B0h,  g_B0h);
    cudaGetSymbolAddress((void**)&B0l,  g_B0l);
    cudaGetSymbolAddress((void**)&W1h,  g_W1h);
    cudaGetSymbolAddress((void**)&W1l,  g_W1l);
    cudaGetSymbolAddress((void**)&W2h,  g_W2h);
    cudaGetSymbolAddress((void**)&W2l,  g_W2l);
    cudaGetSymbolAddress((void**)&bias0, g_bias0);

    static bool attr_done = false;
    if (!attr_done) {
        cudaFuncSetAttribute(bgemm_pipe0,  cudaFuncAttributeMaxDynamicSharedMemorySize, PIPE_SMEM);
        cudaFuncSetAttribute(fused_mlp<2>, cudaFuncAttributeMaxDynamicSharedMemorySize, FUSED_SMEM);
        cudaFuncSetAttribute(fused_mlp<3>, cudaFuncAttributeMaxDynamicSharedMemorySize, FUSED_SMEM);
        cudaFuncSetAttribute(fused_mlp<4>, cudaFuncAttributeMaxDynamicSharedMemorySize, FUSED_SMEM);
        attr_done = true;
    }

    dim3 grid1((N_NODES + 127) / 128, 1);
    dim3 grid2((N_NODES + 127) / 128, 2);

    pack_all<<<512, 256>>>(lsw, ldw, lsb, ldb, w1, w2);
    pack_x<<<(N_NODES * 128 + 255) / 256, 256>>>(x);
    hist_kernel<<<(N_EDGES + 255) / 256, 256>>>(dstp);

    // Launch #4 (profiled): input projection GEMM
    bgemm_pipe0<<<grid2, 256, PIPE_SMEM>>>(xh, xl, B0h, B0l, bias0, xsd,
                                           N_NODES, 256, 256);

    scan_local_kernel<<<SCAN_NB, SCAN_B>>>();
    scan_bsum_kernel<<<1, 128>>>();
    scan_add_kernel<<<(N_NODES + 255) / 256, 256>>>();
    scatter_kernel<<<(N_EDGES + 255) / 256, 256>>>(src, dstp, eattr);

    for (int l = 0; l < NLAYERS; l++) {
        if (l == 0)
            gather_kernel<<<(N_NODES * 32 + 255) / 256, 256>>>(
                xsd, 256, xsd + 128, ew + l * H, ebp + l * H, t, l);
        else
            gather_kernel<<<(N_NODES * 32 + 255) / 256, 256>>>(
                xsr, 128, xsr, ew + l * H, ebp + l * H, t, l);

        if (l == 0)
            fused_mlp<4><<<grid1, 256, FUSED_SMEM>>>(
                obh, obl, W1h + l * 16384, W1l + l * 16384,
                W2h + l * 16384, W2l + l * 16384,
                b1 + l * H2, bg + l * H2, bb + l * H2, bm + l * H2, bv + l * H2,
                b2 + l * H, hbuf, xsr,
                ng + (l + 1) * H, nb + (l + 1) * H, nm + (l + 1) * H, nv + (l + 1) * H,
                N_NODES);
        else if (l < NLAYERS - 1)
            fused_mlp<3><<<grid1, 256, FUSED_SMEM>>>(
                obh, obl, W1h + l * 16384, W1l + l * 16384,
                W2h + l * 16384, W2l + l * 16384,
                b1 + l * H2, bg + l * H2, bb + l * H2, bm + l * H2, bv + l * H2,
                b2 + l * H, hbuf, xsr,
                ng + (l + 1) * H, nb + (l + 1) * H, nm + (l + 1) * H, nv + (l + 1) * H,
                N_NODES);
        else
            fused_mlp<2><<<grid1, 256, FUSED_SMEM>>>(
                obh, obl, W1h + l * 16384, W1l + l * 16384,
                W2h + l * 16384, W2l + l * 16384,
                b1 + l * H2, bg + l * H2, bb + l * H2, bm + l * H2, bv + l * H2,
                b2 + l * H, hbuf, nullptr,
                nullptr, nullptr, nullptr, nullptr,
                N_NODES);
    }

    pool_kernel<<<(N_NODES + POOL_CHUNK - 1) / POOL_CHUNK, H>>>(batch, ng, nb, nm, nv);
    cls_kernel<<<1, 128>>>(clinical, cw, cb, out);
}

// round 8
// speedup vs baseline: 4.0347x; 1.0247x over previous
#include <cuda_runtime.h>
#include <math.h>

// Problem dims (fixed by dataset)
#define N_NODES 50000
#define N_EDGES 500000
#define C_IN    256
#define H       128
#define H2      256
#define NLAYERS 4
#define NGRAPH  64
#define KCLIN   8
#define NCLS    2
#define EPS_MSG 1e-7f
#define EPS_BN  1e-5f

#define SCAN_B  512
#define SCAN_NB ((N_NODES + SCAN_B - 1) / SCAN_B)   // 98
#define SMS 136    // B smem row stride in words (mod 32 == 8 -> conflict-free)
#define ASTRIDE 20 // A stage row stride (20*tg+tq distinct mod 32)
#define MIDSTRIDE 132 // mid row stride (4*tg+tq distinct mod 32)

// ---------------------------------------------------------------------------
// Scratch (device globals; no allocation allowed)
// ---------------------------------------------------------------------------
__device__ float    g_xsd [N_NODES * 256];   // layer-0 src|dst projections
__device__ float    g_xs  [N_NODES * H];     // r buffer (layers >= 1)
__device__ float    g_h   [N_NODES * H];
__device__ unsigned g_obufh[N_NODES * 64];   // gather out, packed bf16x2 hi
__device__ unsigned g_obufl[N_NODES * 64];
__device__ unsigned g_xh  [N_NODES * 128];   // x pre-split packed
__device__ unsigned g_xl  [N_NODES * 128];
__device__ float    g_pool[NGRAPH * H];
__device__ float    g_cnt [NGRAPH];

// Pre-split weights (packed bf16x2 pairs along K)
__device__ unsigned g_B0h[128 * 256], g_B0l[128 * 256];
__device__ float    g_bias0[256];
__device__ unsigned g_W1h[NLAYERS * 64 * 256], g_W1l[NLAYERS * 64 * 256];
__device__ unsigned g_W2h[NLAYERS * 128 * 128], g_W2l[NLAYERS * 128 * 128];

// CSR build scratch
__device__ int  g_count[N_NODES];
__device__ int  g_row  [N_NODES + 1];
__device__ int  g_bsum [128];
__device__ int2 g_edges[N_EDGES];

// ---------------------------------------------------------------------------
// helpers
// ---------------------------------------------------------------------------
__device__ __forceinline__ unsigned packbf(float lo, float hi) {
    unsigned r;
    asm("cvt.rn.bf16x2.f32 %0, %1, %2;" : "=r"(r) : "f"(hi), "f"(lo));
    return r;
}
__device__ __forceinline__ float2 unpackbf(unsigned p) {
    float2 f;
    f.x = __uint_as_float(p << 16);
    f.y = __uint_as_float(p & 0xffff0000u);
    return f;
}
__device__ __forceinline__ void split2(float a, float b, unsigned& h, unsigned& l) {
    h = packbf(a, b);
    float2 f = unpackbf(h);
    l = packbf(a - f.x, b - f.y);
}
__device__ __forceinline__ void mma_bf16(float c[4],
                                         unsigned a0, unsigned a1, unsigned a2, unsigned a3,
                                         unsigned b0, unsigned b1) {
    asm volatile(
        "mma.sync.aligned.m16n8k16.row.col.f32.bf16.bf16.f32 "
        "{%0,%1,%2,%3}, {%4,%5,%6,%7}, {%8,%9}, {%0,%1,%2,%3};"
        : "+f"(c[0]), "+f"(c[1]), "+f"(c[2]), "+f"(c[3])
        : "r"(a0), "r"(a1), "r"(a2), "r"(a3), "r"(b0), "r"(b1));
}
__device__ __forceinline__ void cp_async16(void* smem, const void* gmem) {
    unsigned sa = (unsigned)__cvta_generic_to_shared(smem);
    asm volatile("cp.async.cg.shared.global [%0], [%1], 16;\n"
                 :: "r"(sa), "l"(gmem));
}
__device__ __forceinline__ void cp_async16p(void* smem, const void* gmem, bool pred) {
    unsigned sa = (unsigned)__cvta_generic_to_shared(smem);
    int sz = pred ? 16 : 0;
    asm volatile("cp.async.cg.shared.global [%0], [%1], 16, %2;\n"
                 :: "r"(sa), "l"(gmem), "r"(sz));
}
__device__ __forceinline__ void cp_commit() {
    asm volatile("cp.async.commit_group;\n" ::);
}
template<int W> __device__ __forceinline__ void cp_wait() {
    asm volatile("cp.async.wait_group %0;\n" :: "n"(W));
}

// ---------------------------------------------------------------------------
// pack_all: zero accumulators + pre-split all weights (one launch)
// ---------------------------------------------------------------------------
__global__ void pack_all(const float* __restrict__ lsw, const float* __restrict__ ldw,
                         const float* __restrict__ lsb, const float* __restrict__ ldb,
                         const float* __restrict__ w1, const float* __restrict__ w2)
{
    int i = blockIdx.x * blockDim.x + threadIdx.x;
    int stride = gridDim.x * blockDim.x;
    for (int k = i; k < N_NODES; k += stride) g_count[k] = 0;
    if (i < NGRAPH * H) g_pool[i] = 0.f;
    if (i < NGRAPH) g_cnt[i] = 0.f;
    if (i < 256) g_bias0[i] = (i < 128) ? lsb[i] : ldb[i - 128];

    for (int idx = i; idx < 128 * 256; idx += stride) {
        int k2 = idx >> 8, n = idx & 255;
        float v0, v1;
        if (n < 128) { v0 = lsw[(2*k2)*128 + n];       v1 = lsw[(2*k2+1)*128 + n]; }
        else         { v0 = ldw[(2*k2)*128 + n - 128]; v1 = ldw[(2*k2+1)*128 + n - 128]; }
        unsigned h, l; split2(v0, v1, h, l);
        g_B0h[idx] = h; g_B0l[idx] = l;
    }
    for (int idx = i; idx < NLAYERS * 64 * 256; idx += stride) {
        int l = idx >> 14, rem = idx & 16383;
        int k2 = rem >> 8, n = rem & 255;
        const float* base = w1 + (long)l * 128 * 256;
        unsigned h, lo; split2(base[(2*k2)*256 + n], base[(2*k2+1)*256 + n], h, lo);
        g_W1h[idx] = h; g_W1l[idx] = lo;
    }
    for (int idx = i; idx < NLAYERS * 128 * 128; idx += stride) {
        int l = idx >> 14, rem = idx & 16383;
        int k2 = rem >> 7, n = rem & 127;
        const float* base = w2 + (long)l * 256 * 128;
        unsigned h, lo; split2(base[(2*k2)*128 + n], base[(2*k2+1)*128 + n], h, lo);
        g_W2h[idx] = h; g_W2l[idx] = lo;
    }
}

// pack_x: pre-split node features into packed bf16x2 hi/lo
__global__ void pack_x(const float* __restrict__ x) {
    int idx = blockIdx.x * blockDim.x + threadIdx.x;
    if (idx >= N_NODES * 128) return;
    int row = idx >> 7, k2 = idx & 127;
    float2 v = *reinterpret_cast<const float2*>(x + (long)row * 256 + 2 * k2);
    unsigned h, l; split2(v.x, v.y, h, l);
    g_xh[idx] = h; g_xl[idx] = l;
}

// ---------------------------------------------------------------------------
// CSR build
// ---------------------------------------------------------------------------
__global__ void hist_kernel(const int* __restrict__ dst) {
    int i = blockIdx.x * blockDim.x + threadIdx.x;
    if (i < N_EDGES) atomicAdd(&g_count[dst[i]], 1);
}

__global__ void scan_local_kernel() {
    __shared__ int sh[SCAN_B];
    int tid = threadIdx.x;
    int i = blockIdx.x * SCAN_B + tid;
    int v = (i < N_NODES) ? g_count[i] : 0;
    sh[tid] = v;
    __syncthreads();
    for (int off = 1; off < SCAN_B; off <<= 1) {
        int t = (tid >= off) ? sh[tid - off] : 0;
        __syncthreads();
        sh[tid] += t;
        __syncthreads();
    }
    if (i < N_NODES) g_row[i] = sh[tid] - v;
    if (tid == SCAN_B - 1) g_bsum[blockIdx.x] = sh[tid];
}

__global__ void scan_bsum_kernel() {
    __shared__ int sh[128];
    int tid = threadIdx.x;
    int v = (tid < SCAN_NB) ? g_bsum[tid] : 0;
    sh[tid] = v;
    __syncthreads();
    for (int off = 1; off < 128; off <<= 1) {
        int t = (tid >= off) ? sh[tid - off] : 0;
        __syncthreads();
        sh[tid] += t;
        __syncthreads();
    }
    if (tid < SCAN_NB) g_bsum[tid] = sh[tid] - v;
}

__global__ void scan_add_kernel() {
    int i = blockIdx.x * blockDim.x + threadIdx.x;
    if (i < N_NODES) {
        int r = g_row[i] + g_bsum[i / SCAN_B];
        g_row[i] = r;
        g_count[i] = r;
    }
    if (i == 0) g_row[N_NODES] = N_EDGES;
}

__global__ void scatter_kernel(const int* __restrict__ src,
                               const int* __restrict__ dst,
                               const float* __restrict__ eattr) {
    int e = blockIdx.x * blockDim.x + threadIdx.x;
    if (e >= N_EDGES) return;
    int d = dst[e];
    int pos = atomicAdd(&g_count[d], 1);
    g_edges[pos] = make_int2(src[e], __float_as_int(eattr[e]));
}

// ---------------------------------------------------------------------------
// Gather: one warp per dst node; softmax aggregation without max-shift.
// ---------------------------------------------------------------------------
__global__ __launch_bounds__(256)
void gather_kernel(const float* __restrict__ xs, int ldx,
                   const float* __restrict__ xd,
                   const float* __restrict__ ew,
                   const float* __restrict__ eb,
                   const float* __restrict__ tptr, int l)
{
    int warp = (blockIdx.x * blockDim.x + threadIdx.x) >> 5;
    if (warp >= N_NODES) return;
    int lane = threadIdx.x & 31;
    int c0 = lane * 4;

    float4 w4 = *reinterpret_cast<const float4*>(ew + c0);
    float4 b4 = *reinterpret_cast<const float4*>(eb + c0);
    float tv = tptr[l];

    int e0 = g_row[warp];
    int e1 = g_row[warp + 1];

    float n0 = 0.f, n1 = 0.f, n2 = 0.f, n3 = 0.f;
    float d0 = 0.f, d1 = 0.f, d2 = 0.f, d3 = 0.f;

#pragma unroll 4
    for (int e = e0; e < e1; e++) {
        int2 ed = g_edges[e];
        int   s  = ed.x;
        float al = __int_as_float(ed.y);
        float4 x4 = *reinterpret_cast<const float4*>(xs + (long)s * ldx + c0);

        float m0 = fmaxf(fmaf(al, w4.x, b4.x) + x4.x, 0.f) + EPS_MSG;
        float m1 = fmaxf(fmaf(al, w4.y, b4.y) + x4.y, 0.f) + EPS_MSG;
        float m2 = fmaxf(fmaf(al, w4.z, b4.z) + x4.z, 0.f) + EPS_MSG;
        float m3 = fmaxf(fmaf(al, w4.w, b4.w) + x4.w, 0.f) + EPS_MSG;

        float z0 = __expf(m0 * tv);
        float z1 = __expf(m1 * tv);
        float z2 = __expf(m2 * tv);
        float z3 = __expf(m3 * tv);

        d0 += z0; d1 += z1; d2 += z2; d3 += z3;
        n0 = fmaf(m0, z0, n0); n1 = fmaf(m1, z1, n1);
        n2 = fmaf(m2, z2, n2); n3 = fmaf(m3, z3, n3);
    }

    float4 xv = *reinterpret_cast<const float4*>(xd + (long)warp * ldx + c0);
    float ox = n0 / fmaxf(d0, 1e-16f) + xv.x;
    float oy = n1 / fmaxf(d1, 1e-16f) + xv.y;
    float oz = n2 / fmaxf(d2, 1e-16f) + xv.z;
    float ow = n3 / fmaxf(d3, 1e-16f) + xv.w;

    unsigned h0, l0, h1, l1;
    split2(ox, oy, h0, l0);
    split2(oz, ow, h1, l1);
    int p = warp * 64 + (c0 >> 1);
    *reinterpret_cast<uint2*>(g_obufh + p) = make_uint2(h0, h1);
    *reinterpret_cast<uint2*>(g_obufl + p) = make_uint2(l0, l1);
}

// ---------------------------------------------------------------------------
// Pipelined GEMM, 512 threads (16 warps, 4x4 grid, 32x32 warp tile).
// C = A[M,K] @ B[K,N] + bias (A pre-split packed). Used for input projection.
// ---------------------------------------------------------------------------
#define PIPE_SMEM ((2*128*ASTRIDE*2 + 2*16*SMS*2) * 4)

__global__ __launch_bounds__(512)
void bgemm_pipe0(const unsigned* __restrict__ Ah_g, const unsigned* __restrict__ Al_g,
                 const unsigned* __restrict__ Bh_g, const unsigned* __restrict__ Bl_g,
                 const float* __restrict__ bias, float* __restrict__ C,
                 int M, int N, int K)
{
    extern __shared__ unsigned smem_[];
    unsigned* Ah = smem_;
    unsigned* Al = Ah + 2 * 128 * ASTRIDE;
    unsigned* Bh = Al + 2 * 128 * ASTRIDE;
    unsigned* Bl = Bh + 2 * 16 * SMS;
#define AHS(s,r,k) Ah[((s)*128 + (r)) * ASTRIDE + (k)]
#define ALS(s,r,k) Al[((s)*128 + (r)) * ASTRIDE + (k)]
#define BHS(s,r,n) Bh[((s)*16 + (r)) * SMS + (n)]
#define BLS(s,r,n) Bl[((s)*16 + (r)) * SMS + (n)]

    int tid = threadIdx.x;
    int wid = tid >> 5, lane = tid & 31;
    int tg = lane >> 2, tq = lane & 3;
    int warpM = wid >> 2, warpN = wid & 3;      // 4 x 4 warps
    int rowBase = blockIdx.x * 128;
    int colBase = blockIdx.y * 128;
    int mW = warpM * 32, nW = warpN * 32;
    int K2 = K >> 1;

    float acc[2][4][4];
#pragma unroll
    for (int mi = 0; mi < 2; mi++)
#pragma unroll
        for (int ni = 0; ni < 4; ni++)
#pragma unroll
            for (int r = 0; r < 4; r++) acc[mi][ni][r] = 0.f;

    auto load_stage = [&](int s, int k0) {
        int k20 = k0 >> 1;
        {   // A: 128 rows x 16 k2 words, 512 thr x 4 words
            int r = tid >> 2;
            int kc2 = (tid & 3) * 4;
            int gr = rowBase + r;
            bool ok = gr < M;
            long off = (long)(ok ? gr : 0) * K2 + k20 + kc2;
            cp_async16p(&AHS(s, r, kc2), Ah_g + off, ok);
            cp_async16p(&ALS(s, r, kc2), Al_g + off, ok);
        }
        {   // B: 16 rows x 128 words
            int kr = tid >> 5;
            int nc = (tid & 31) * 4;
            long off = (long)(k20 + kr) * N + colBase + nc;
            cp_async16(&BHS(s, kr, nc), Bh_g + off);
            cp_async16(&BLS(s, kr, nc), Bl_g + off);
        }
        cp_commit();
    };

    int nIter = K >> 5;
    load_stage(0, 0);

    for (int it = 0; it < nIter; it++) {
        if (it + 1 < nIter) {
            load_stage((it + 1) & 1, (it + 1) << 5);
            cp_wait<1>();
        } else {
            cp_wait<0>();
        }
        __syncthreads();

        int s = it & 1;
#pragma unroll
        for (int kk = 0; kk < 2; kk++) {
            int k2a = kk * 8 + tq, k2b = k2a + 4;
            unsigned bh0[4], bh1[4], bl0[4], bl1[4];
#pragma unroll
            for (int ni = 0; ni < 4; ni++) {
                int n = nW + ni * 8 + tg;
                bh0[ni] = BHS(s, k2a, n); bh1[ni] = BHS(s, k2b, n);
                bl0[ni] = BLS(s, k2a, n); bl1[ni] = BLS(s, k2b, n);
            }
#pragma unroll
            for (int mi = 0; mi < 2; mi++) {
                int m = mW + mi * 16 + tg;
                unsigned ah0 = AHS(s, m, k2a), ah1 = AHS(s, m + 8, k2a);
                unsigned ah2 = AHS(s, m, k2b), ah3 = AHS(s, m + 8, k2b);
                unsigned al0 = ALS(s, m, k2a), al1 = ALS(s, m + 8, k2a);
                unsigned al2 = ALS(s, m, k2b), al3 = ALS(s, m + 8, k2b);
#pragma unroll
                for (int ni = 0; ni < 4; ni++) {
                    mma_bf16(acc[mi][ni], ah0, ah1, ah2, ah3, bh0[ni], bh1[ni]);
                    mma_bf16(acc[mi][ni], ah0, ah1, ah2, ah3, bl0[ni], bl1[ni]);
                    mma_bf16(acc[mi][ni], al0, al1, al2, al3, bh0[ni], bh1[ni]);
                }
            }
        }
        __syncthreads();
    }

#pragma unroll
    for (int ni = 0; ni < 4; ni++) {
        int c = colBase + nW + ni * 8 + tq * 2;
        float2 bi = *reinterpret_cast<const float2*>(bias + c);
#pragma unroll
        for (int mi = 0; mi < 2; mi++) {
            int r0 = rowBase + mW + mi * 16 + tg;
#pragma unroll
            for (int half = 0; half < 2; half++) {
                int row = r0 + half * 8;
                if (row >= M) continue;
                float vL = acc[mi][ni][half * 2 + 0] + bi.x;
                float vH = acc[mi][ni][half * 2 + 1] + bi.y;
                *reinterpret_cast<float2*>(C + (long)row * N + c) = make_float2(vL, vH);
            }
        }
    }
#undef AHS
#undef ALS
#undef BHS
#undef BLS
}

// ---------------------------------------------------------------------------
// Fused MLP, 512 threads: per 128-node tile computes
//   mid = split(relu(bn(obuf @ W1 + b1)))   (mid resident in smem)
//   v   = mid @ W2 + b2
//   MODE 4: h  = v; R = relu(bn_next(h))
//   MODE 3: h += v; R = relu(bn_next(h))
//   MODE 2: h += v
// ---------------------------------------------------------------------------
#define FUSED_SMEM ((2*128*ASTRIDE*2 + 2*16*SMS*2 + 128*MIDSTRIDE*2) * 4)

template<int MODE>
__global__ __launch_bounds__(512)
void fused_mlp(const unsigned* __restrict__ Ah_g, const unsigned* __restrict__ Al_g,
               const unsigned* __restrict__ W1h_g, const unsigned* __restrict__ W1l_g,
               const unsigned* __restrict__ W2h_g, const unsigned* __restrict__ W2l_g,
               const float* __restrict__ b1,
               const float* __restrict__ bnAg, const float* __restrict__ bnAb,
               const float* __restrict__ bnAm, const float* __restrict__ bnAv,
               const float* __restrict__ b2,
               float* __restrict__ C, float* __restrict__ R,
               const float* __restrict__ bnNg, const float* __restrict__ bnNb,
               const float* __restrict__ bnNm, const float* __restrict__ bnNv,
               int M)
{
    extern __shared__ unsigned smem_[];
    unsigned* Ah = smem_;                          // [2][128][ASTRIDE]
    unsigned* Al = Ah + 2 * 128 * ASTRIDE;
    unsigned* Bh = Al + 2 * 128 * ASTRIDE;         // [2][16][SMS]
    unsigned* Bl = Bh + 2 * 16 * SMS;
    unsigned* MidH = Bl + 2 * 16 * SMS;            // [128][MIDSTRIDE]
    unsigned* MidL = MidH + 128 * MIDSTRIDE;
#define AHS(s,r,k) Ah[((s)*128 + (r)) * ASTRIDE + (k)]
#define ALS(s,r,k) Al[((s)*128 + (r)) * ASTRIDE + (k)]
#define BHS(s,r,n) Bh[((s)*16 + (r)) * SMS + (n)]
#define BLS(s,r,n) Bl[((s)*16 + (r)) * SMS + (n)]
#define MIDH(r,k)  MidH[(r) * MIDSTRIDE + (k)]
#define MIDL(r,k)  MidL[(r) * MIDSTRIDE + (k)]

    int tid = threadIdx.x;
    int wid = tid >> 5, lane = tid & 31;
    int tg = lane >> 2, tq = lane & 3;
    int warpM = wid >> 2, warpN = wid & 3;         // 4 x 4 warps
    int rowBase = blockIdx.x * 128;
    int mW = warpM * 32, nW = warpN * 32;

    float acc[2][4][4];

    // ---------------- Phase A: mid = split(relu(bn(obuf @ W1 + b1))) --------
    for (int halfN = 0; halfN < 2; halfN++) {
        int colBase = halfN * 128;
#pragma unroll
        for (int mi = 0; mi < 2; mi++)
#pragma unroll
            for (int ni = 0; ni < 4; ni++)
#pragma unroll
                for (int r = 0; r < 4; r++) acc[mi][ni][r] = 0.f;

        auto load_stageA = [&](int s, int k20) {
            {   // A: 128 rows x 16 k2 (K2 = 64)
                int r = tid >> 2;
                int kc2 = (tid & 3) * 4;
                int gr = rowBase + r;
                bool ok = gr < M;
                long off = (long)(ok ? gr : 0) * 64 + k20 + kc2;
                cp_async16p(&AHS(s, r, kc2), Ah_g + off, ok);
                cp_async16p(&ALS(s, r, kc2), Al_g + off, ok);
            }
            {   // B: 16 rows x 128 cols of W1 (N = 256)
                int kr = tid >> 5;
                int nc = (tid & 31) * 4;
                long off = (long)(k20 + kr) * 256 + colBase + nc;
                cp_async16(&BHS(s, kr, nc), W1h_g + off);
                cp_async16(&BLS(s, kr, nc), W1l_g + off);
            }
            cp_commit();
        };

        load_stageA(0, 0);
        for (int it = 0; it < 4; it++) {
            if (it + 1 < 4) { load_stageA((it + 1) & 1, (it + 1) * 16); cp_wait<1>(); }
            else            { cp_wait<0>(); }
            __syncthreads();
            int s = it & 1;
#pragma unroll
            for (int kk = 0; kk < 2; kk++) {
                int k2a = kk * 8 + tq, k2b = k2a + 4;
                unsigned bh0[4], bh1[4], bl0[4], bl1[4];
#pragma unroll
                for (int ni = 0; ni < 4; ni++) {
                    int n = nW + ni * 8 + tg;
                    bh0[ni] = BHS(s, k2a, n); bh1[ni] = BHS(s, k2b, n);
                    bl0[ni] = BLS(s, k2a, n); bl1[ni] = BLS(s, k2b, n);
                }
#pragma unroll
                for (int mi = 0; mi < 2; mi++) {
                    int m = mW + mi * 16 + tg;
                    unsigned ah0 = AHS(s, m, k2a), ah1 = AHS(s, m + 8, k2a);
                    unsigned ah2 = AHS(s, m, k2b), ah3 = AHS(s, m + 8, k2b);
                    unsigned al0 = ALS(s, m, k2a), al1 = ALS(s, m + 8, k2a);
                    unsigned al2 = ALS(s, m, k2b), al3 = ALS(s, m + 8, k2b);
#pragma unroll
                    for (int ni = 0; ni < 4; ni++) {
                        mma_bf16(acc[mi][ni], ah0, ah1, ah2, ah3, bh0[ni], bh1[ni]);
                        mma_bf16(acc[mi][ni], ah0, ah1, ah2, ah3, bl0[ni], bl1[ni]);
                        mma_bf16(acc[mi][ni], al0, al1, al2, al3, bh0[ni], bh1[ni]);
                    }
                }
            }
            __syncthreads();
        }

        // epilogue -> mid smem (bn + relu + split)
#pragma unroll
        for (int ni = 0; ni < 4; ni++) {
            int c = colBase + nW + ni * 8 + tq * 2;
            float2 bi = *reinterpret_cast<const float2*>(b1 + c);
            float2 gg = *reinterpret_cast<const float2*>(bnAg + c);
            float2 gb = *reinterpret_cast<const float2*>(bnAb + c);
            float2 gm = *reinterpret_cast<const float2*>(bnAm + c);
            float2 gv = *reinterpret_cast<const float2*>(bnAv + c);
            float scL = gg.x * rsqrtf(gv.x + EPS_BN), shL = gb.x - gm.x * scL;
            float scH = gg.y * rsqrtf(gv.y + EPS_BN), shH = gb.y - gm.y * scH;
            int pcol = c >> 1;
#pragma unroll
            for (int mi = 0; mi < 2; mi++) {
#pragma unroll
                for (int hr = 0; hr < 2; hr++) {
                    int rl = mW + mi * 16 + tg + hr * 8;
                    float vL = acc[mi][ni][hr * 2 + 0] + bi.x;
                    float vH = acc[mi][ni][hr * 2 + 1] + bi.y;
                    float tL = fmaxf(fmaf(vL, scL, shL), 0.f);
                    float tH = fmaxf(fmaf(vH, scH, shH), 0.f);
                    unsigned hp, lp; split2(tL, tH, hp, lp);
                    MIDH(rl, pcol) = hp;
                    MIDL(rl, pcol) = lp;
                }
            }
        }
        __syncthreads();
    }

    // ---------------- Phase B: v = mid @ W2 + b2 ---------------------------
#pragma unroll
    for (int mi = 0; mi < 2; mi++)
#pragma unroll
        for (int ni = 0; ni < 4; ni++)
#pragma unroll
            for (int r = 0; r < 4; r++) acc[mi][ni][r] = 0.f;

    auto load_stageB = [&](int s, int k20) {
        int kr = tid >> 5;
        int nc = (tid & 31) * 4;
        long off = (long)(k20 + kr) * 128 + nc;
        cp_async16(&BHS(s, kr, nc), W2h_g + off);
        cp_async16(&BLS(s, kr, nc), W2l_g + off);
        cp_commit();
    };

    load_stageB(0, 0);
    for (int it = 0; it < 8; it++) {
        if (it + 1 < 8) { load_stageB((it + 1) & 1, (it + 1) * 16); cp_wait<1>(); }
        else            { cp_wait<0>(); }
        __syncthreads();
        int s = it & 1;
#pragma unroll
        for (int kk = 0; kk < 2; kk++) {
            int k2a = kk * 8 + tq, k2b = k2a + 4;
            int g2a = it * 16 + k2a, g2b = it * 16 + k2b;
            unsigned bh0[4], bh1[4], bl0[4], bl1[4];
#pragma unroll
            for (int ni = 0; ni < 4; ni++) {
                int n = nW + ni * 8 + tg;
                bh0[ni] = BHS(s, k2a, n); bh1[ni] = BHS(s, k2b, n);
                bl0[ni] = BLS(s, k2a, n); bl1[ni] = BLS(s, k2b, n);
            }
#pragma unroll
            for (int mi = 0; mi < 2; mi++) {
                int m = mW + mi * 16 + tg;
                unsigned ah0 = MIDH(m, g2a), ah1 = MIDH(m + 8, g2a);
                unsigned ah2 = MIDH(m, g2b), ah3 = MIDH(m + 8, g2b);
                unsigned al0 = MIDL(m, g2a), al1 = MIDL(m + 8, g2a);
                unsigned al2 = MIDL(m, g2b), al3 = MIDL(m + 8, g2b);
#pragma unroll
                for (int ni = 0; ni < 4; ni++) {
                    mma_bf16(acc[mi][ni], ah0, ah1, ah2, ah3, bh0[ni], bh1[ni]);
                    mma_bf16(acc[mi][ni], ah0, ah1, ah2, ah3, bl0[ni], bl1[ni]);
                    mma_bf16(acc[mi][ni], al0, al1, al2, al3, bh0[ni], bh1[ni]);
                }
            }
        }
        __syncthreads();
    }

    // Final epilogue
#pragma unroll
    for (int ni = 0; ni < 4; ni++) {
        int c = nW + ni * 8 + tq * 2;
        float2 bi = *reinterpret_cast<const float2*>(b2 + c);
        float scL = 1.f, shL = 0.f, scH = 1.f, shH = 0.f;
        if (MODE == 3 || MODE == 4) {
            float2 gg = *reinterpret_cast<const float2*>(bnNg + c);
            float2 gb = *reinterpret_cast<const float2*>(bnNb + c);
            float2 gm = *reinterpret_cast<const float2*>(bnNm + c);
            float2 gv = *reinterpret_cast<const float2*>(bnNv + c);
            scL = gg.x * rsqrtf(gv.x + EPS_BN); shL = gb.x - gm.x * scL;
            scH = gg.y * rsqrtf(gv.y + EPS_BN); shH = gb.y - gm.y * scH;
        }
#pragma unroll
        for (int mi = 0; mi < 2; mi++) {
            int r0 = rowBase + mW + mi * 16 + tg;
#pragma unroll
            for (int hr = 0; hr < 2; hr++) {
                int row = r0 + hr * 8;
                if (row >= M) continue;
                float vL = acc[mi][ni][hr * 2 + 0] + bi.x;
                float vH = acc[mi][ni][hr * 2 + 1] + bi.y;
                float2* p = reinterpret_cast<float2*>(C + (long)row * 128 + c);
                if (MODE == 4) {
                    *p = make_float2(vL, vH);
                    *reinterpret_cast<float2*>(R + (long)row * 128 + c) = make_float2(
                        fmaxf(fmaf(vL, scL, shL), 0.f), fmaxf(fmaf(vH, scH, shH), 0.f));
                } else if (MODE == 3) {
                    float2 old = *p;
                    float hL = old.x + vL, hH = old.y + vH;
                    *p = make_float2(hL, hH);
                    *reinterpret_cast<float2*>(R + (long)row * 128 + c) = make_float2(
                        fmaxf(fmaf(hL, scL, shL), 0.f), fmaxf(fmaf(hH, scH, shH), 0.f));
                } else { // MODE 2
                    float2 old = *p;
                    *p = make_float2(old.x + vL, old.y + vH);
                }
            }
        }
    }
#undef AHS
#undef ALS
#undef BHS
#undef BLS
#undef MIDH
#undef MIDL
}

// ---------------------------------------------------------------------------
#define POOL_CHUNK 64
__global__ void pool_kernel(const int* __restrict__ batch,
                            const float* __restrict__ gg,
                            const float* __restrict__ gb,
                            const float* __restrict__ gm,
                            const float* __restrict__ gv)
{
    int c = threadIdx.x;
    int n0 = blockIdx.x * POOL_CHUNK;
    int n1 = min(n0 + POOL_CHUNK, N_NODES);
    float sc = gg[c] * rsqrtf(gv[c] + EPS_BN);
    float sh = gb[c] - gm[c] * sc;

    int curg = batch[n0];
    float acc = 0.f, cnt = 0.f;
    for (int n = n0; n < n1; n++) {
        int bg = batch[n];
        float val = fmaxf(fmaf(g_h[(long)n * H + c], sc, sh), 0.f);
        if (bg != curg) {
            atomicAdd(&g_pool[curg * H + c], acc);
            if (c == 0) atomicAdd(&g_cnt[curg], cnt);
            acc = 0.f; cnt = 0.f; curg = bg;
        }
        acc += val; cnt += 1.f;
    }
    atomicAdd(&g_pool[curg * H + c], acc);
    if (c == 0) atomicAdd(&g_cnt[curg], cnt);
}

__global__ void cls_kernel(const float* __restrict__ clinical,
                           const float* __restrict__ cw,
                           const float* __restrict__ cb,
                           float* __restrict__ out)
{
    int tid = threadIdx.x;
    if (tid >= NGRAPH * NCLS) return;
    int g = tid >> 1;
    int c = tid & 1;
    float inv = 1.f / fmaxf(g_cnt[g], 1.f);
    float acc = cb[c];
    for (int j = 0; j < H; j++)
        acc += g_pool[g * H + j] * inv * cw[j * NCLS + c];
    for (int k = 0; k < KCLIN; k++)
        acc += clinical[g * KCLIN + k] * cw[(H + k) * NCLS + c];
    out[g * NCLS + c] = acc;
}

// ---------------------------------------------------------------------------
extern "C" void kernel_launch(void* const* d_in, const int* in_sizes, int n_in,
                              void* d_out, int out_size)
{
    const float* x        = (const float*)d_in[0];
    const int*   ei       = (const int*)  d_in[1];
    const float* eattr    = (const float*)d_in[2];
    const int*   batch    = (const int*)  d_in[3];
    const float* clinical = (const float*)d_in[4];
    const float* lsw = (const float*)d_in[5],  *lsb = (const float*)d_in[6];
    const float* ldw = (const float*)d_in[7],  *ldb = (const float*)d_in[8];
    const float* ew  = (const float*)d_in[9],  *ebp = (const float*)d_in[10];
    const float* t   = (const float*)d_in[11];
    const float* w1  = (const float*)d_in[12], *b1  = (const float*)d_in[13];
    const float* bg  = (const float*)d_in[14], *bb  = (const float*)d_in[15];
    const float* bm  = (const float*)d_in[16], *bv  = (const float*)d_in[17];
    const float* w2  = (const float*)d_in[18], *b2  = (const float*)d_in[19];
    const float* ng  = (const float*)d_in[20], *nb  = (const float*)d_in[21];
    const float* nm  = (const float*)d_in[22], *nv  = (const float*)d_in[23];
    const float* cw  = (const float*)d_in[24], *cb  = (const float*)d_in[25];
    float* out = (float*)d_out;

    const int* src = ei;
    const int* dstp = ei + N_EDGES;

    float *xsd, *xsr, *hbuf, *bias0;
    unsigned *obh, *obl, *xh, *xl, *B0h, *B0l, *W1h, *W1l, *W2h, *W2l;
    cudaGetSymbolAddress((void**)&xsd,  g_xsd);
    cudaGetSymbolAddress((void**)&xsr,  g_xs);
    cudaGetSymbolAddress((void**)&hbuf, g_h);
    cudaGetSymbolAddress((void**)&obh,  g_obufh);
    cudaGetSymbolAddress((void**)&obl,  g_obufl);
    cudaGetSymbolAddress((void**)&xh,   g_xh);
    cudaGetSymbolAddress((void**)&xl,   g_xl);
    cudaGetSymbolAddress((void**)&B0h,  g_B0h);
    cudaGetSymbolAddress((void**)&B0l,  g_B0l);
    cudaGetSymbolAddress((void**)&W1h,  g_W1h);
    cudaGetSymbolAddress((void**)&W1l,  g_W1l);
    cudaGetSymbolAddress((void**)&W2h,  g_W2h);
    cudaGetSymbolAddress((void**)&W2l,  g_W2l);
    cudaGetSymbolAddress((void**)&bias0, g_bias0);

    static bool attr_done = false;
    if (!attr_done) {
        cudaFuncSetAttribute(bgemm_pipe0,  cudaFuncAttributeMaxDynamicSharedMemorySize, PIPE_SMEM);
        cudaFuncSetAttribute(fused_mlp<2>, cudaFuncAttributeMaxDynamicSharedMemorySize, FUSED_SMEM);
        cudaFuncSetAttribute(fused_mlp<3>, cudaFuncAttributeMaxDynamicSharedMemorySize, FUSED_SMEM);
        cudaFuncSetAttribute(fused_mlp<4>, cudaFuncAttributeMaxDynamicSharedMemorySize, FUSED_SMEM);
        attr_done = true;
    }

    dim3 grid1((N_NODES + 127) / 128, 1);
    dim3 grid2((N_NODES + 127) / 128, 2);

    pack_all<<<512, 256>>>(lsw, ldw, lsb, ldb, w1, w2);
    pack_x<<<(N_NODES * 128 + 255) / 256, 256>>>(x);
    hist_kernel<<<(N_EDGES + 255) / 256, 256>>>(dstp);

    // Launch #4 (profiled): input projection GEMM
    bgemm_pipe0<<<grid2, 512, PIPE_SMEM>>>(xh, xl, B0h, B0l, bias0, xsd,
                                           N_NODES, 256, 256);

    scan_local_kernel<<<SCAN_NB, SCAN_B>>>();
    scan_bsum_kernel<<<1, 128>>>();
    scan_add_kernel<<<(N_NODES + 255) / 256, 256>>>();
    scatter_kernel<<<(N_EDGES + 255) / 256, 256>>>(src, dstp, eattr);

    for (int l = 0; l < NLAYERS; l++) {
        if (l == 0)
            gather_kernel<<<(N_NODES * 32 + 255) / 256, 256>>>(
                xsd, 256, xsd + 128, ew + l * H, ebp + l * H, t, l);
        else
            gather_kernel<<<(N_NODES * 32 + 255) / 256, 256>>>(
                xsr, 128, xsr, ew + l * H, ebp + l * H, t, l);

        if (l == 0)
            fused_mlp<4><<<grid1, 512, FUSED_SMEM>>>(
                obh, obl, W1h + l * 16384, W1l + l * 16384,
                W2h + l * 16384, W2l + l * 16384,
                b1 + l * H2, bg + l * H2, bb + l * H2, bm + l * H2, bv + l * H2,
                b2 + l * H, hbuf, xsr,
                ng + (l + 1) * H, nb + (l + 1) * H, nm + (l + 1) * H, nv + (l + 1) * H,
                N_NODES);
        else if (l < NLAYERS - 1)
            fused_mlp<3><<<grid1, 512, FUSED_SMEM>>>(
                obh, obl, W1h + l * 16384, W1l + l * 16384,
                W2h + l * 16384, W2l + l * 16384,
                b1 + l * H2, bg + l * H2, bb + l * H2, bm + l * H2, bv + l * H2,
                b2 + l * H, hbuf, xsr,
                ng + (l + 1) * H, nb + (l + 1) * H, nm + (l + 1) * H, nv + (l + 1) * H,
                N_NODES);
        else
            fused_mlp<2><<<grid1, 512, FUSED_SMEM>>>(
                obh, obl, W1h + l * 16384, W1l + l * 16384,
                W2h + l * 16384, W2l + l * 16384,
                b1 + l * H2, bg + l * H2, bb + l * H2, bm + l * H2, bv + l * H2,
                b2 + l * H, hbuf, nullptr,
                nullptr, nullptr, nullptr, nullptr,
                N_NODES);
    }

    pool_kernel<<<(N_NODES + POOL_CHUNK - 1) / POOL_CHUNK, H>>>(batch, ng, nb, nm, nv);
    cls_kernel<<<1, 128>>>(clinical, cw, cb, out);
}